// round 8
// baseline (speedup 1.0000x reference)
#include <cuda_runtime.h>
#include <cuda_bf16.h>
#include <math.h>
#include <stdint.h>

#define B_    64
#define CIN_  256
#define HID_  256
#define COUT_ 10
#define EPS_  1e-5f

// ---------------------------------------------------------------------------
// Device globals (no runtime allocation allowed)
// ---------------------------------------------------------------------------
__device__ float g_kfeat[B_ * HID_ * 25];        // (64,256,5,5)
__device__ float g_sfeat[B_ * HID_ * 841];       // (64,256,29,29)
__device__ float g_h    [B_ * HID_ * 625];       // (64,256,25,25)
// packed bf16 hi/lo weights, smem-ready order
__device__ __align__(16) uint32_t g_wk_hi[9 * 256 * 128], g_wk_lo[9 * 256 * 128];
__device__ __align__(16) uint32_t g_ws_hi[9 * 256 * 128], g_ws_lo[9 * 256 * 128];
__device__ __align__(16) uint32_t g_wd_hi[256 * 384],     g_wd_lo[256 * 384];
__device__ __align__(16) uint32_t g_wh1_hi[256 * 128],    g_wh1_lo[256 * 128];
// packed bf16 hi/lo inputs: [icpair 128][b 64][HW]
__device__ __align__(16) uint32_t g_kin_hi[128 * 64 * 49],  g_kin_lo[128 * 64 * 49];
__device__ __align__(16) uint32_t g_sin_hi[128 * 64 * 961], g_sin_lo[128 * 64 * 961];
// packed bf16 hi/lo activations: [kpair][n=40000]
__device__ __align__(16) uint32_t g_featP_hi[384 * 40000], g_featP_lo[384 * 40000];
__device__ __align__(16) uint32_t g_f2P_hi [128 * 40000], g_f2P_lo [128 * 40000];

// ---------------------------------------------------------------------------
// PTX helpers (baseline ISA only; compiles for plain compute_103)
// ---------------------------------------------------------------------------
__device__ __forceinline__ void mma_bf16(float* c, const uint32_t* a,
                                         const uint32_t* b) {
    asm volatile(
        "mma.sync.aligned.m16n8k16.row.col.f32.bf16.bf16.f32 "
        "{%0,%1,%2,%3}, {%4,%5,%6,%7}, {%8,%9}, {%0,%1,%2,%3};"
        : "+f"(c[0]), "+f"(c[1]), "+f"(c[2]), "+f"(c[3])
        : "r"(a[0]), "r"(a[1]), "r"(a[2]), "r"(a[3]), "r"(b[0]), "r"(b[1]));
}

__device__ __forceinline__ void ldm4(uint32_t* d, uint32_t addr) {
    asm volatile("ldmatrix.sync.aligned.m8n8.x4.shared.b16 {%0,%1,%2,%3}, [%4];"
                 : "=r"(d[0]), "=r"(d[1]), "=r"(d[2]), "=r"(d[3]) : "r"(addr));
}

__device__ __forceinline__ uint32_t smem_u32(const void* p) {
    uint32_t a;
    asm("{ .reg .u64 t; cvta.to.shared.u64 t, %1; cvt.u32.u64 %0, t; }"
        : "=r"(a) : "l"(p));
    return a;
}

#define CP_ASYNC16(dst, src) \
    asm volatile("cp.async.cg.shared.global [%0], [%1], 16;" :: "r"(dst), "l"(src))
#define CP_COMMIT()  asm volatile("cp.async.commit_group;")
#define CP_WAIT0()   asm volatile("cp.async.wait_group 0;" ::: "memory")

__device__ __forceinline__ void split2(float a, float b, uint32_t& hi, uint32_t& lo) {
    __nv_bfloat162 h = __floats2bfloat162_rn(a, b);
    hi = *reinterpret_cast<uint32_t*>(&h);
    float ra = a - __bfloat162float(h.x);
    float rb = b - __bfloat162float(h.y);
    __nv_bfloat162 l = __floats2bfloat162_rn(ra, rb);
    lo = *reinterpret_cast<uint32_t*>(&l);
}

__device__ __forceinline__ void split1_u16(float v, uint16_t& hi, uint16_t& lo) {
    __nv_bfloat16 h = __float2bfloat16_rn(v);
    hi = *reinterpret_cast<uint16_t*>(&h);
    float r = v - __bfloat162float(h);
    __nv_bfloat16 l = __float2bfloat16_rn(r);
    lo = *reinterpret_cast<uint16_t*>(&l);
}

// ---------------------------------------------------------------------------
// Prep kernels
// ---------------------------------------------------------------------------
__global__ void prep_w3(const float* __restrict__ w,
                        uint32_t* __restrict__ oh, uint32_t* __restrict__ ol) {
    int idx = blockIdx.x * 256 + threadIdx.x;
    if (idx >= 9 * 256 * 128) return;
    int tap = idx >> 15;
    int rem = idx & 32767;
    int oc = rem >> 7, p = rem & 127;
    float a = w[(size_t)oc * 2304 + (2 * p) * 9 + tap];
    float b = w[(size_t)oc * 2304 + (2 * p + 1) * 9 + tap];
    split2(a, b, oh[idx], ol[idx]);
}

template <int K>
__global__ void prep_w1(const float* __restrict__ w,
                        uint32_t* __restrict__ oh, uint32_t* __restrict__ ol) {
    int idx = blockIdx.x * 256 + threadIdx.x;
    if (idx >= 256 * (K / 2)) return;
    int oc = idx / (K / 2), kp = idx - oc * (K / 2);
    split2(w[(size_t)oc * K + 2 * kp], w[(size_t)oc * K + 2 * kp + 1],
           oh[idx], ol[idx]);
}

template <int HW>
__global__ void prep_in(const float* __restrict__ in,
                        uint32_t* __restrict__ oh, uint32_t* __restrict__ ol) {
    int idx = blockIdx.x * 256 + threadIdx.x;
    if (idx >= 128 * 64 * HW) return;
    int p = idx / (64 * HW);
    int rem = idx - p * (64 * HW);
    int b = rem / HW, pix = rem - b * HW;
    const float* src = in + (size_t)b * 256 * HW + (2 * p) * HW + pix;
    split2(src[0], src[HW], oh[idx], ol[idx]);
}

// ---------------------------------------------------------------------------
// Tensor-core GEMM (bf16x3): C[oc][n] = sum_k A[oc][k]*B[k][n], + BN (+ReLU)
// MODE 0: implicit-GEMM 3x3 conv (k = tap*256+ic). MODE 1: 1x1 conv.
// EPI 0: fp32 NCHW. EPI 1: packed bf16 hi/lo [kpair][n].
// Block tile M=128 x N=256 x K=32/stage. 8 warps as 2(M) x 4(N); warp 64x64.
// Double-buffered; A via cp.async (issued late, R5-proven order); B prefetch
// split hi/lo around the two kc chunks to bound live registers.
// ---------------------------------------------------------------------------
template <int MODE, int HIN, int WIN, int KT, bool RELU, int EPI>
__global__ void __launch_bounds__(256, 1)
gemm_mma3_kernel(const uint32_t* __restrict__ bH_src, const uint32_t* __restrict__ bL_src,
                 const uint32_t* __restrict__ aH_src, const uint32_t* __restrict__ aL_src,
                 const float* __restrict__ bn, float* __restrict__ out,
                 uint16_t* __restrict__ outH, uint16_t* __restrict__ outL) {
    constexpr int WOUT = WIN - 2;
    constexpr int PXB  = (MODE == 0) ? (HIN - 2) * WOUT : 625;
    constexpr int NP   = 64 * PXB;
    constexpr int HW   = HIN * WIN;
    constexpr int S    = KT / 32;
    constexpr int RSTR = 20;
    constexpr int ATILE = 128 * RSTR;        // 2560 u32
    constexpr int BTILE = 256 * RSTR;        // 5120 u32
    constexpr int BUFSZ = 2 * ATILE + 2 * BTILE;  // 15360 u32 per buffer
    constexpr int AR   = (MODE == 0) ? 128 : (KT / 2);
    constexpr int PLSTR = 64 * HW;

    extern __shared__ uint32_t smem[];
    const uint32_t smb = smem_u32(smem);

    const int tid  = threadIdx.x;
    const int warp = tid >> 5;
    const int lane = tid & 31;
    const int gid  = lane >> 2;
    const int tig  = lane & 3;
    const int wm   = warp >> 2;              // 0..1
    const int wn   = warp & 3;               // 0..3
    const int moff = wm * 64;
    const int noff = wn * 64;

    const int oc0 = blockIdx.y * 128;
    const int p0  = blockIdx.x * 256;

    const int aRow = lane & 15;
    const int aCol = (lane >> 4) * 4;
    const int bRow = (lane & 7) + ((lane >> 4) & 1) * 8;
    const int bCol = ((lane >> 3) & 1) * 4;

    // B gather: thread owns pixel n = p0 + tid
    const int nglob = p0 + tid;
    const bool nvalid = (nglob < NP);
    int bbase = 0;
    if (MODE == 0) {
        int nn = nvalid ? nglob : 0;
        int b = nn / PXB; int rem = nn - b * PXB;
        int y = rem / WOUT; int x = rem - y * WOUT;
        bbase = b * HW + y * WIN + x;
    }

    float acc[4][8][4];
#pragma unroll
    for (int a = 0; a < 4; a++)
#pragma unroll
        for (int b = 0; b < 8; b++)
#pragma unroll
            for (int c = 0; c < 4; c++) acc[a][b][c] = 0.f;

    // part = 0 (hi) / 1 (lo): 16 u32 (one pixel row x 16 k-words)
    auto prefetchB = [&](int s, int part, uint32_t v[4][4]) {
        int tapoff = 0, plane0 = 0;
        if (MODE == 0) {
            int tap = s >> 3; plane0 = (s & 7) * 16;
            tapoff = (tap / 3) * WIN + (tap % 3);
        }
        const uint32_t* src = part ? bL_src : bH_src;
#pragma unroll
        for (int wg = 0; wg < 4; wg++)
#pragma unroll
            for (int j = 0; j < 4; j++) {
                int w = wg * 4 + j;
                long addr = (MODE == 0)
                    ? (long)(plane0 + w) * PLSTR + bbase + tapoff
                    : (long)(s * 16 + w) * 40000 + nglob;
                v[wg][j] = nvalid ? __ldg(src + addr) : 0u;
            }
    };
    auto storeB = [&](int buf, int part, uint32_t v[4][4]) {
        uint32_t* dst0 = &smem[buf * BUFSZ + 2 * ATILE + part * BTILE + tid * RSTR];
#pragma unroll
        for (int wg = 0; wg < 4; wg++)
            *reinterpret_cast<uint4*>(dst0 + wg * 4) =
                make_uint4(v[wg][0], v[wg][1], v[wg][2], v[wg][3]);
    };
    auto stageA = [&](int buf, int s) {
        int abase;
        if (MODE == 0) {
            int tap = s >> 3; int plane0 = (s & 7) * 16;
            abase = tap * 32768 + oc0 * 128 + plane0;
        } else {
            abase = oc0 * (KT / 2) + s * 16;
        }
#pragma unroll
        for (int i = 0; i < 4; i++) {
            int task = tid + 256 * i;
            int hl = task >> 9;
            int rem = task & 511;
            int r = rem >> 2;
            int c = (rem & 3) * 4;
            const uint32_t* src = (hl ? aL_src : aH_src) + abase + r * AR + c;
            uint32_t dst = smb + (buf * BUFSZ + hl * ATILE + r * RSTR + c) * 4;
            CP_ASYNC16(dst, src);
        }
    };

    // consume one kc chunk of buffer buf
    auto mma_kc = [&](int buf, int kc) {
        const uint32_t smA_hi = smb + (buf * BUFSZ) * 4;
        const uint32_t smA_lo = smA_hi + ATILE * 4;
        const uint32_t smB_hi = smA_hi + 2 * ATILE * 4;
        const uint32_t smB_lo = smB_hi + BTILE * 4;
        uint32_t aH[4][4], aL[4][4];
#pragma unroll
        for (int mf = 0; mf < 4; mf++) {
            uint32_t off = ((moff + mf * 16 + aRow) * RSTR + kc * 8 + aCol) * 4;
            ldm4(aH[mf], smA_hi + off);
            ldm4(aL[mf], smA_lo + off);
        }
#pragma unroll
        for (int nfp = 0; nfp < 4; nfp++) {
            uint32_t boff = ((noff + nfp * 16 + bRow) * RSTR + kc * 8 + bCol) * 4;
            uint32_t bHf[4], bLf[4];
            ldm4(bHf, smB_hi + boff);
            ldm4(bLf, smB_lo + boff);
#pragma unroll
            for (int snf = 0; snf < 2; snf++) {
                int nf = nfp * 2 + snf;
#pragma unroll
                for (int mf = 0; mf < 4; mf++) {
                    mma_bf16(acc[mf][nf], aH[mf], &bHf[2 * snf]);
                    mma_bf16(acc[mf][nf], aH[mf], &bLf[2 * snf]);
                    mma_bf16(acc[mf][nf], aL[mf], &bHf[2 * snf]);
                }
            }
        }
    };

    // prologue: fill buf 0
    {
        uint32_t v[4][4];
        prefetchB(0, 0, v);
        storeB(0, 0, v);
        prefetchB(0, 1, v);
        storeB(0, 1, v);
        stageA(0, 0);
        CP_COMMIT();
    }

    for (int s = 0; s < S; s++) {
        const int buf = s & 1;
        CP_WAIT0();
        __syncthreads();

        const bool have = (s + 1 < S);
        uint32_t vpre[4][4];
        if (have) prefetchB(s + 1, 0, vpre);   // hi half of next B

        mma_kc(buf, 0);

        if (have) {
            storeB(buf ^ 1, 0, vpre);
            prefetchB(s + 1, 1, vpre);         // lo half of next B
        }

        mma_kc(buf, 1);

        if (have) {
            storeB(buf ^ 1, 1, vpre);
            stageA(buf ^ 1, s + 1);            // late issue (R5-proven order)
            CP_COMMIT();
        }
    }

    // epilogue: two N-halves of 128 through padded smem
    __syncthreads();
    float* Cs = (float*)smem;                // 128 x 132 fp32 (67584 B)
#pragma unroll
    for (int h2 = 0; h2 < 2; h2++) {
        if ((wn >> 1) == h2) {
            int nbase = noff - h2 * 128;
#pragma unroll
            for (int mf = 0; mf < 4; mf++) {
#pragma unroll
                for (int nf = 0; nf < 8; nf++) {
                    int m0 = moff + mf * 16 + gid;
                    int nl = nbase + nf * 8 + 2 * tig;
                    *(float2*)&Cs[m0 * 132 + nl]       = make_float2(acc[mf][nf][0], acc[mf][nf][1]);
                    *(float2*)&Cs[(m0 + 8) * 132 + nl] = make_float2(acc[mf][nf][2], acc[mf][nf][3]);
                }
            }
        }
        __syncthreads();

        for (int t = warp; t < 128; t += 8) {
            const int oc = oc0 + t;
            const float g  = bn[oc];
            const float be = bn[256 + oc];
            const float mm = bn[512 + oc];
            const float vv = bn[768 + oc];
            const float inv  = g * rsqrtf(vv + EPS_);
            const float bias = be - mm * inv;
#pragma unroll
            for (int cc0 = 0; cc0 < 128; cc0 += 32) {
                int cc = cc0 + lane;
                int n = p0 + h2 * 128 + cc;
                if (n < NP) {
                    float val = Cs[t * 132 + cc] * inv + bias;
                    if (RELU) val = fmaxf(val, 0.f);
                    if (EPI == 0) {
                        int b = n / PXB; int rq = n - b * PXB;
                        out[((size_t)(b * 256 + oc)) * PXB + rq] = val;
                    } else {
                        uint16_t h, l;
                        split1_u16(val, h, l);
                        size_t off = (size_t)(oc >> 1) * 80000 + n * 2 + (oc & 1);
                        outH[off] = h;
                        outL[off] = l;
                    }
                }
            }
        }
        __syncthreads();
    }
}

// ---------------------------------------------------------------------------
// Multi-scale depthwise xcorr; emits packed bf16 hi/lo [kpair][n] directly.
// ---------------------------------------------------------------------------
__global__ void multixcorr_kernel(const float* __restrict__ s,
                                  const float* __restrict__ k,
                                  uint32_t* __restrict__ fh,
                                  uint32_t* __restrict__ fl) {
    const int c = blockIdx.x;
    const int b = blockIdx.y;

    __shared__ float ss[29 * 29];
    __shared__ float kk[25];

    const float* sp = s + ((size_t)b * HID_ + c) * 841;
    const float* kp = k + ((size_t)b * HID_ + c) * 25;

    for (int i = threadIdx.x; i < 841; i += blockDim.x) ss[i] = sp[i];
    if (threadIdx.x < 25) kk[threadIdx.x] = kp[threadIdx.x];
    __syncthreads();

    uint16_t* fH = (uint16_t*)fh;
    uint16_t* fL = (uint16_t*)fl;
    const int half = c & 1;
    const int kp0 = c >> 1;

    for (int p = threadIdx.x; p < 625; p += blockDim.x) {
        const int y = p / 25, x = p - (p / 25) * 25;
        float s_full = 0.f, s_in = 0.f;
#pragma unroll
        for (int dy = 0; dy < 5; dy++)
#pragma unroll
            for (int dx = 0; dx < 5; dx++) {
                float vv = ss[(y + dy) * 29 + (x + dx)] * kk[dy * 5 + dx];
                s_full += vv;
                if (dy >= 1 && dy <= 3 && dx >= 1 && dx <= 3) s_in += vv;
            }
        float s_c = ss[(y + 2) * 29 + (x + 2)] * kk[12];
        const int n = b * 625 + p;
        uint16_t h, l;
        split1_u16(s_full, h, l);
        fH[(size_t)kp0 * 80000 + n * 2 + half] = h;
        fL[(size_t)kp0 * 80000 + n * 2 + half] = l;
        split1_u16(s_in, h, l);
        fH[(size_t)(128 + kp0) * 80000 + n * 2 + half] = h;
        fL[(size_t)(128 + kp0) * 80000 + n * 2 + half] = l;
        split1_u16(s_c, h, l);
        fH[(size_t)(256 + kp0) * 80000 + n * 2 + half] = h;
        fL[(size_t)(256 + kp0) * 80000 + n * 2 + half] = l;
    }
}

// ---------------------------------------------------------------------------
// Final 1x1: (B,256,625) x (10,256) + bias -> (B,10,625). grid (B, 5).
// ---------------------------------------------------------------------------
__global__ void conv1x1_out_kernel(const float* __restrict__ in,
                                   const float* __restrict__ w,
                                   const float* __restrict__ bias,
                                   float* __restrict__ out) {
    const int b = blockIdx.x;
    const int chunk = blockIdx.y;

    __shared__ float wsm[COUT_ * HID_];
    for (int i = threadIdx.x; i < COUT_ * HID_; i += blockDim.x) wsm[i] = w[i];
    __syncthreads();

    const float* ib = in + (size_t)b * HID_ * 625;
    float* ob = out + (size_t)b * COUT_ * 625;

    const int pend = min(625, (chunk + 1) * 125);
    for (int p = chunk * 125 + threadIdx.x; p < pend; p += blockDim.x) {
        float acc[COUT_];
#pragma unroll
        for (int o = 0; o < COUT_; o++) acc[o] = bias[o];
        for (int c = 0; c < HID_; c++) {
            float vv = ib[(size_t)c * 625 + p];
#pragma unroll
            for (int o = 0; o < COUT_; o++) acc[o] = fmaf(vv, wsm[o * HID_ + c], acc[o]);
        }
#pragma unroll
        for (int o = 0; o < COUT_; o++) ob[(size_t)o * 625 + p] = acc[o];
    }
}

// ---------------------------------------------------------------------------
extern "C" void kernel_launch(void* const* d_in, const int* in_sizes, int n_in,
                              void* d_out, int out_size) {
    const float* kernel_in = (const float*)d_in[0];
    const float* search_in = (const float*)d_in[1];
    const float* wk  = (const float*)d_in[2];
    const float* bnk = (const float*)d_in[3];
    const float* ws  = (const float*)d_in[4];
    const float* bns = (const float*)d_in[5];
    const float* wd  = (const float*)d_in[6];
    const float* bnd = (const float*)d_in[7];
    const float* wh1 = (const float*)d_in[8];
    const float* bnh = (const float*)d_in[9];
    const float* wh2 = (const float*)d_in[10];
    const float* bh2 = (const float*)d_in[11];
    float* out = (float*)d_out;

    float *kfeat, *sfeat, *h;
    uint32_t *wkh, *wkl, *wsh, *wsl, *wdh, *wdl, *wh1h, *wh1l;
    uint32_t *kinh, *kinl, *sinh, *sinl, *fph, *fpl, *f2h, *f2l;
    cudaGetSymbolAddress((void**)&kfeat, g_kfeat);
    cudaGetSymbolAddress((void**)&sfeat, g_sfeat);
    cudaGetSymbolAddress((void**)&h,     g_h);
    cudaGetSymbolAddress((void**)&wkh, g_wk_hi);  cudaGetSymbolAddress((void**)&wkl, g_wk_lo);
    cudaGetSymbolAddress((void**)&wsh, g_ws_hi);  cudaGetSymbolAddress((void**)&wsl, g_ws_lo);
    cudaGetSymbolAddress((void**)&wdh, g_wd_hi);  cudaGetSymbolAddress((void**)&wdl, g_wd_lo);
    cudaGetSymbolAddress((void**)&wh1h, g_wh1_hi); cudaGetSymbolAddress((void**)&wh1l, g_wh1_lo);
    cudaGetSymbolAddress((void**)&kinh, g_kin_hi); cudaGetSymbolAddress((void**)&kinl, g_kin_lo);
    cudaGetSymbolAddress((void**)&sinh, g_sin_hi); cudaGetSymbolAddress((void**)&sinl, g_sin_lo);
    cudaGetSymbolAddress((void**)&fph, g_featP_hi); cudaGetSymbolAddress((void**)&fpl, g_featP_lo);
    cudaGetSymbolAddress((void**)&f2h, g_f2P_hi);  cudaGetSymbolAddress((void**)&f2l, g_f2P_lo);

    constexpr int SMEM = 2 * 15360 * 4;  // 122880

    cudaFuncSetAttribute(gemm_mma3_kernel<0, 7, 7, 2304, true, 0>,
                         cudaFuncAttributeMaxDynamicSharedMemorySize, SMEM);
    cudaFuncSetAttribute(gemm_mma3_kernel<0, 31, 31, 2304, true, 0>,
                         cudaFuncAttributeMaxDynamicSharedMemorySize, SMEM);
    cudaFuncSetAttribute(gemm_mma3_kernel<1, 3, 3, 768, false, 1>,
                         cudaFuncAttributeMaxDynamicSharedMemorySize, SMEM);
    cudaFuncSetAttribute(gemm_mma3_kernel<1, 3, 3, 256, true, 0>,
                         cudaFuncAttributeMaxDynamicSharedMemorySize, SMEM);

    prep_in<961><<<(128 * 64 * 961 + 255) / 256, 256>>>(search_in, sinh, sinl);
    prep_w3<<<(9 * 256 * 128 + 255) / 256, 256>>>(ws, wsh, wsl);
    prep_w3<<<(9 * 256 * 128 + 255) / 256, 256>>>(wk, wkh, wkl);
    prep_w1<768><<<(256 * 384 + 255) / 256, 256>>>(wd, wdh, wdl);
    prep_w1<256><<<(256 * 128 + 255) / 256, 256>>>(wh1, wh1h, wh1l);

    // search branch conv3x3 -> g_sfeat ; NP=53824 -> 211 N-tiles
    gemm_mma3_kernel<0, 31, 31, 2304, true, 0><<<dim3(211, 2), 256, SMEM>>>(
        sinh, sinl, wsh, wsl, bns, sfeat, nullptr, nullptr);

    prep_in<49><<<(128 * 64 * 49 + 255) / 256, 256>>>(kernel_in, kinh, kinl);

    // kernel branch conv3x3 -> g_kfeat ; NP=1600 -> 7 N-tiles
    gemm_mma3_kernel<0, 7, 7, 2304, true, 0><<<dim3(7, 2), 256, SMEM>>>(
        kinh, kinl, wkh, wkl, bnk, kfeat, nullptr, nullptr);
    // xcorr -> packed featP
    multixcorr_kernel<<<dim3(HID_, B_), 256>>>(sfeat, kfeat, fph, fpl);
    // wd + bn -> packed f2P ; 157 N-tiles
    gemm_mma3_kernel<1, 3, 3, 768, false, 1><<<dim3(157, 2), 256, SMEM>>>(
        fph, fpl, wdh, wdl, bnd, nullptr, (uint16_t*)f2h, (uint16_t*)f2l);
    // wh1 + bn + relu -> g_h
    gemm_mma3_kernel<1, 3, 3, 256, true, 0><<<dim3(157, 2), 256, SMEM>>>(
        f2h, f2l, wh1h, wh1l, bnh, h, nullptr, nullptr);
    // wh2 + bias -> out
    conv1x1_out_kernel<<<dim3(B_, 5), 128>>>(h, wh2, bh2, out);
}

// round 9
// speedup vs baseline: 1.1459x; 1.1459x over previous
#include <cuda_runtime.h>
#include <cuda_bf16.h>
#include <math.h>
#include <stdint.h>

#define B_    64
#define CIN_  256
#define HID_  256
#define COUT_ 10
#define EPS_  1e-5f

// ---------------------------------------------------------------------------
// Device globals (no runtime allocation allowed)
// ---------------------------------------------------------------------------
__device__ float g_kfeat[B_ * HID_ * 25];        // (64,256,5,5)
__device__ float g_sfeat[B_ * HID_ * 841];       // (64,256,29,29)
__device__ float g_h    [B_ * HID_ * 625];       // (64,256,25,25)
// packed bf16 hi/lo weights, smem-ready order
__device__ __align__(16) uint32_t g_wk_hi[9 * 256 * 128], g_wk_lo[9 * 256 * 128];
__device__ __align__(16) uint32_t g_ws_hi[9 * 256 * 128], g_ws_lo[9 * 256 * 128];
__device__ __align__(16) uint32_t g_wd_hi[256 * 384],     g_wd_lo[256 * 384];
__device__ __align__(16) uint32_t g_wh1_hi[256 * 128],    g_wh1_lo[256 * 128];
// packed bf16 hi/lo inputs: [icpair 128][b 64][HW]
__device__ __align__(16) uint32_t g_kin_hi[128 * 64 * 49],  g_kin_lo[128 * 64 * 49];
__device__ __align__(16) uint32_t g_sin_hi[128 * 64 * 961], g_sin_lo[128 * 64 * 961];
// packed bf16 hi/lo activations: [kpair][n=40000]
__device__ __align__(16) uint32_t g_featP_hi[384 * 40000], g_featP_lo[384 * 40000];
__device__ __align__(16) uint32_t g_f2P_hi [128 * 40000], g_f2P_lo [128 * 40000];

// ---------------------------------------------------------------------------
// PTX helpers (baseline ISA only; compiles for plain compute_103)
// ---------------------------------------------------------------------------
__device__ __forceinline__ void mma_bf16(float* c, const uint32_t* a,
                                         const uint32_t* b) {
    asm volatile(
        "mma.sync.aligned.m16n8k16.row.col.f32.bf16.bf16.f32 "
        "{%0,%1,%2,%3}, {%4,%5,%6,%7}, {%8,%9}, {%0,%1,%2,%3};"
        : "+f"(c[0]), "+f"(c[1]), "+f"(c[2]), "+f"(c[3])
        : "r"(a[0]), "r"(a[1]), "r"(a[2]), "r"(a[3]), "r"(b[0]), "r"(b[1]));
}

__device__ __forceinline__ void ldm4(uint32_t* d, uint32_t addr) {
    asm volatile("ldmatrix.sync.aligned.m8n8.x4.shared.b16 {%0,%1,%2,%3}, [%4];"
                 : "=r"(d[0]), "=r"(d[1]), "=r"(d[2]), "=r"(d[3]) : "r"(addr));
}

__device__ __forceinline__ uint32_t smem_u32(const void* p) {
    uint32_t a;
    asm("{ .reg .u64 t; cvta.to.shared.u64 t, %1; cvt.u32.u64 %0, t; }"
        : "=r"(a) : "l"(p));
    return a;
}

#define CP_ASYNC16(dst, src) \
    asm volatile("cp.async.cg.shared.global [%0], [%1], 16;" :: "r"(dst), "l"(src))
#define CP_COMMIT()  asm volatile("cp.async.commit_group;")
#define CP_WAIT0()   asm volatile("cp.async.wait_group 0;" ::: "memory")

__device__ __forceinline__ void split2(float a, float b, uint32_t& hi, uint32_t& lo) {
    __nv_bfloat162 h = __floats2bfloat162_rn(a, b);
    hi = *reinterpret_cast<uint32_t*>(&h);
    float ra = a - __bfloat162float(h.x);
    float rb = b - __bfloat162float(h.y);
    __nv_bfloat162 l = __floats2bfloat162_rn(ra, rb);
    lo = *reinterpret_cast<uint32_t*>(&l);
}

__device__ __forceinline__ void split1_u16(float v, uint16_t& hi, uint16_t& lo) {
    __nv_bfloat16 h = __float2bfloat16_rn(v);
    hi = *reinterpret_cast<uint16_t*>(&h);
    float r = v - __bfloat162float(h);
    __nv_bfloat16 l = __float2bfloat16_rn(r);
    lo = *reinterpret_cast<uint16_t*>(&l);
}

// pack two bf16-hi (and two bf16-lo) of (a,b) into u32 words
__device__ __forceinline__ void split2w(float a, float b, uint32_t& hw, uint32_t& lw) {
    uint16_t ha, la, hb, lb;
    split1_u16(a, ha, la);
    split1_u16(b, hb, lb);
    hw = (uint32_t)ha | ((uint32_t)hb << 16);
    lw = (uint32_t)la | ((uint32_t)lb << 16);
}

// ---------------------------------------------------------------------------
// Prep kernels
// ---------------------------------------------------------------------------
__global__ void prep_w3(const float* __restrict__ w,
                        uint32_t* __restrict__ oh, uint32_t* __restrict__ ol) {
    int idx = blockIdx.x * 256 + threadIdx.x;
    if (idx >= 9 * 256 * 128) return;
    int tap = idx >> 15;
    int rem = idx & 32767;
    int oc = rem >> 7, p = rem & 127;
    float a = w[(size_t)oc * 2304 + (2 * p) * 9 + tap];
    float b = w[(size_t)oc * 2304 + (2 * p + 1) * 9 + tap];
    split2(a, b, oh[idx], ol[idx]);
}

template <int K>
__global__ void prep_w1(const float* __restrict__ w,
                        uint32_t* __restrict__ oh, uint32_t* __restrict__ ol) {
    int idx = blockIdx.x * 256 + threadIdx.x;
    if (idx >= 256 * (K / 2)) return;
    int oc = idx / (K / 2), kp = idx - oc * (K / 2);
    split2(w[(size_t)oc * K + 2 * kp], w[(size_t)oc * K + 2 * kp + 1],
           oh[idx], ol[idx]);
}

template <int HW>
__global__ void prep_in(const float* __restrict__ in,
                        uint32_t* __restrict__ oh, uint32_t* __restrict__ ol) {
    int idx = blockIdx.x * 256 + threadIdx.x;
    if (idx >= 128 * 64 * HW) return;
    int p = idx / (64 * HW);
    int rem = idx - p * (64 * HW);
    int b = rem / HW, pix = rem - b * HW;
    const float* src = in + (size_t)b * 256 * HW + (2 * p) * HW + pix;
    split2(src[0], src[HW], oh[idx], ol[idx]);
}

// ---------------------------------------------------------------------------
// Tensor-core GEMM (bf16x3): C[oc][n] = sum_k A[oc][k]*B[k][n], + BN (+ReLU)
// MODE 0: implicit-GEMM 3x3 conv (k = tap*256+ic). MODE 1: 1x1 conv.
// EPI 0: fp32 NCHW. EPI 1: packed bf16 hi/lo [kpair][n].
// R5-proven config: tile M=128 x N=128 x K=32/stage, RSTR=20, double-buffered,
// late-issue stageA. Grid: x = oc half (2), y = pixel tile (consecutive CTA
// ids share the B tile for L2 timing locality).
// ---------------------------------------------------------------------------
template <int MODE, int HIN, int WIN, int KT, bool RELU, int EPI>
__global__ void __launch_bounds__(256, 2)
gemm_mma2_kernel(const uint32_t* __restrict__ bH_src, const uint32_t* __restrict__ bL_src,
                 const uint32_t* __restrict__ aH_src, const uint32_t* __restrict__ aL_src,
                 const float* __restrict__ bn, float* __restrict__ out,
                 uint16_t* __restrict__ outH, uint16_t* __restrict__ outL) {
    constexpr int WOUT = WIN - 2;
    constexpr int PXB  = (MODE == 0) ? (HIN - 2) * WOUT : 625;
    constexpr int NP   = 64 * PXB;
    constexpr int HW   = HIN * WIN;
    constexpr int S    = KT / 32;
    constexpr int RSTR = 20;
    constexpr int TILE = 128 * RSTR;
    constexpr int AR   = (MODE == 0) ? 128 : (KT / 2);
    constexpr int PLSTR = 64 * HW;

    extern __shared__ uint32_t smem[];
    const uint32_t smb = smem_u32(smem);

    const int tid  = threadIdx.x;
    const int warp = tid >> 5;
    const int lane = tid & 31;
    const int gid  = lane >> 2;
    const int tig  = lane & 3;
    const int moff = (warp >> 1) * 32;
    const int noff = (warp & 1) * 64;

    const int oc0 = blockIdx.x * 128;   // 2 M-halves adjacent in CTA id order
    const int p0  = blockIdx.y * 128;

    const int aRow = lane & 15;
    const int aCol = (lane >> 4) * 4;
    const int bRow = (lane & 7) + ((lane >> 4) & 1) * 8;
    const int bCol = ((lane >> 3) & 1) * 4;

    const int nloc  = tid & 127;
    const int nglob = p0 + nloc;
    const bool nvalid = (nglob < NP);
    int bbase = 0;
    if (MODE == 0) {
        int nn = nvalid ? nglob : 0;
        int b = nn / PXB; int rem = nn - b * PXB;
        int y = rem / WOUT; int x = rem - y * WOUT;
        bbase = b * HW + y * WIN + x;
    }

    float acc[2][8][4];
#pragma unroll
    for (int a = 0; a < 2; a++)
#pragma unroll
        for (int b = 0; b < 8; b++)
#pragma unroll
            for (int c = 0; c < 4; c++) acc[a][b][c] = 0.f;

    auto prefetchB = [&](int s, uint32_t v[4][4]) {
        int tapoff = 0, plane0 = 0;
        if (MODE == 0) {
            int tap = s >> 3; plane0 = (s & 7) * 16;
            tapoff = (tap / 3) * WIN + (tap % 3);
        }
#pragma unroll
        for (int i = 0; i < 4; i++) {
            int task = tid + 256 * i;
            int hl = task >> 9;
            int wg = (task >> 7) & 3;
            const uint32_t* src = hl ? bL_src : bH_src;
#pragma unroll
            for (int j = 0; j < 4; j++) {
                int w = wg * 4 + j;
                long addr = (MODE == 0)
                    ? (long)(plane0 + w) * PLSTR + bbase + tapoff
                    : (long)(s * 16 + w) * 40000 + nglob;
                v[i][j] = nvalid ? __ldg(src + addr) : 0u;
            }
        }
    };
    auto storeB = [&](int buf, uint32_t v[4][4]) {
#pragma unroll
        for (int i = 0; i < 4; i++) {
            int task = tid + 256 * i;
            int hl = task >> 9;
            int wg = (task >> 7) & 3;
            uint32_t* dst = &smem[(buf * 4 + 2 + hl) * TILE + nloc * RSTR + wg * 4];
            *reinterpret_cast<uint4*>(dst) =
                make_uint4(v[i][0], v[i][1], v[i][2], v[i][3]);
        }
    };
    auto stageA = [&](int buf, int s) {
        int abase;
        if (MODE == 0) {
            int tap = s >> 3; int plane0 = (s & 7) * 16;
            abase = tap * 32768 + oc0 * 128 + plane0;
        } else {
            abase = oc0 * (KT / 2) + s * 16;
        }
#pragma unroll
        for (int i = 0; i < 4; i++) {
            int task = tid + 256 * i;
            int hl = task >> 9;
            int rem = task & 511;
            int r = rem >> 2;
            int c = (rem & 3) * 4;
            const uint32_t* src = (hl ? aL_src : aH_src) + abase + r * AR + c;
            uint32_t dst = smb + ((buf * 4 + hl) * TILE + r * RSTR + c) * 4;
            CP_ASYNC16(dst, src);
        }
    };

    // prologue: fill buf 0
    {
        uint32_t v[4][4];
        prefetchB(0, v);
        storeB(0, v);
        stageA(0, 0);
        CP_COMMIT();
    }

    for (int s = 0; s < S; s++) {
        const int buf = s & 1;
        CP_WAIT0();
        __syncthreads();

        const bool have = (s + 1 < S);
        uint32_t vpre[4][4];
        if (have) prefetchB(s + 1, vpre);

        const uint32_t smA_hi = smb + (buf * 4 + 0) * TILE * 4;
        const uint32_t smA_lo = smb + (buf * 4 + 1) * TILE * 4;
        const uint32_t smB_hi = smb + (buf * 4 + 2) * TILE * 4;
        const uint32_t smB_lo = smb + (buf * 4 + 3) * TILE * 4;
#pragma unroll
        for (int kc = 0; kc < 2; kc++) {
            uint32_t aH[2][4], aL[2][4];
#pragma unroll
            for (int mf = 0; mf < 2; mf++) {
                uint32_t off = ((moff + mf * 16 + aRow) * RSTR + kc * 8 + aCol) * 4;
                ldm4(aH[mf], smA_hi + off);
                ldm4(aL[mf], smA_lo + off);
            }
#pragma unroll
            for (int nfp = 0; nfp < 4; nfp++) {
                uint32_t boff = ((noff + nfp * 16 + bRow) * RSTR + kc * 8 + bCol) * 4;
                uint32_t bHf[4], bLf[4];
                ldm4(bHf, smB_hi + boff);
                ldm4(bLf, smB_lo + boff);
#pragma unroll
                for (int snf = 0; snf < 2; snf++) {
                    int nf = nfp * 2 + snf;
#pragma unroll
                    for (int mf = 0; mf < 2; mf++) {
                        mma_bf16(acc[mf][nf], aH[mf], &bHf[2 * snf]);
                        mma_bf16(acc[mf][nf], aH[mf], &bLf[2 * snf]);
                        mma_bf16(acc[mf][nf], aL[mf], &bHf[2 * snf]);
                    }
                }
            }
        }

        if (have) {
            storeB(buf ^ 1, vpre);
            stageA(buf ^ 1, s + 1);   // late issue (R5-proven order)
            CP_COMMIT();
        }
    }

    // epilogue
    __syncthreads();
    float* Cs = (float*)smem;                // 128 x 132 fp32 (67584 B)
#pragma unroll
    for (int mf = 0; mf < 2; mf++) {
#pragma unroll
        for (int nf = 0; nf < 8; nf++) {
            int m0 = moff + mf * 16 + gid;
            int nl = noff + nf * 8 + 2 * tig;
            *(float2*)&Cs[m0 * 132 + nl]       = make_float2(acc[mf][nf][0], acc[mf][nf][1]);
            *(float2*)&Cs[(m0 + 8) * 132 + nl] = make_float2(acc[mf][nf][2], acc[mf][nf][3]);
        }
    }
    __syncthreads();

    for (int t = warp; t < 128; t += 8) {
        const int oc = oc0 + t;
        const float g  = bn[oc];
        const float be = bn[256 + oc];
        const float mm = bn[512 + oc];
        const float vv = bn[768 + oc];
        const float inv  = g * rsqrtf(vv + EPS_);
        const float bias = be - mm * inv;
#pragma unroll
        for (int cc0 = 0; cc0 < 128; cc0 += 32) {
            int cc = cc0 + lane;
            int n = p0 + cc;
            if (n < NP) {
                float val = Cs[t * 132 + cc] * inv + bias;
                if (RELU) val = fmaxf(val, 0.f);
                if (EPI == 0) {
                    int b = n / PXB; int rq = n - b * PXB;
                    out[((size_t)(b * 256 + oc)) * PXB + rq] = val;
                } else {
                    uint16_t h, l;
                    split1_u16(val, h, l);
                    size_t off = (size_t)(oc >> 1) * 80000 + n * 2 + (oc & 1);
                    outH[off] = h;
                    outL[off] = l;
                }
            }
        }
    }
}

// ---------------------------------------------------------------------------
// Multi-scale depthwise xcorr, paired channels: block = (kp0, b) handles
// channels 2*kp0 and 2*kp0+1, emitting full u32 packed words (coalesced).
// ---------------------------------------------------------------------------
__global__ void multixcorr_kernel(const float* __restrict__ s,
                                  const float* __restrict__ k,
                                  uint32_t* __restrict__ fh,
                                  uint32_t* __restrict__ fl) {
    const int kp0 = blockIdx.x;   // 0..127
    const int b   = blockIdx.y;

    __shared__ float ss[2][841];
    __shared__ float kk[2][25];

    const float* sp = s + ((size_t)b * HID_ + 2 * kp0) * 841;
    const float* kp = k + ((size_t)b * HID_ + 2 * kp0) * 25;

    for (int i = threadIdx.x; i < 2 * 841; i += blockDim.x)
        ss[i / 841][i % 841] = sp[i];
    if (threadIdx.x < 50) kk[threadIdx.x / 25][threadIdx.x % 25] = kp[threadIdx.x];
    __syncthreads();

    for (int p = threadIdx.x; p < 625; p += blockDim.x) {
        const int y = p / 25, x = p - (p / 25) * 25;
        float f0[2], f1[2], f2[2];
#pragma unroll
        for (int h = 0; h < 2; h++) {
            float s_full = 0.f, s_in = 0.f;
#pragma unroll
            for (int dy = 0; dy < 5; dy++)
#pragma unroll
                for (int dx = 0; dx < 5; dx++) {
                    float vv = ss[h][(y + dy) * 29 + (x + dx)] * kk[h][dy * 5 + dx];
                    s_full += vv;
                    if (dy >= 1 && dy <= 3 && dx >= 1 && dx <= 3) s_in += vv;
                }
            f0[h] = s_full;
            f1[h] = s_in;
            f2[h] = ss[h][(y + 2) * 29 + (x + 2)] * kk[h][12];
        }
        const int n = b * 625 + p;
        uint32_t hw, lw;
        split2w(f0[0], f0[1], hw, lw);
        fh[(size_t)kp0 * 40000 + n] = hw;
        fl[(size_t)kp0 * 40000 + n] = lw;
        split2w(f1[0], f1[1], hw, lw);
        fh[(size_t)(128 + kp0) * 40000 + n] = hw;
        fl[(size_t)(128 + kp0) * 40000 + n] = lw;
        split2w(f2[0], f2[1], hw, lw);
        fh[(size_t)(256 + kp0) * 40000 + n] = hw;
        fl[(size_t)(256 + kp0) * 40000 + n] = lw;
    }
}

// ---------------------------------------------------------------------------
// Final 1x1: (B,256,625) x (10,256) + bias -> (B,10,625). grid (B, 5).
// ---------------------------------------------------------------------------
__global__ void conv1x1_out_kernel(const float* __restrict__ in,
                                   const float* __restrict__ w,
                                   const float* __restrict__ bias,
                                   float* __restrict__ out) {
    const int b = blockIdx.x;
    const int chunk = blockIdx.y;

    __shared__ float wsm[COUT_ * HID_];
    for (int i = threadIdx.x; i < COUT_ * HID_; i += blockDim.x) wsm[i] = w[i];
    __syncthreads();

    const float* ib = in + (size_t)b * HID_ * 625;
    float* ob = out + (size_t)b * COUT_ * 625;

    const int pend = min(625, (chunk + 1) * 125);
    for (int p = chunk * 125 + threadIdx.x; p < pend; p += blockDim.x) {
        float acc[COUT_];
#pragma unroll
        for (int o = 0; o < COUT_; o++) acc[o] = bias[o];
        for (int c = 0; c < HID_; c++) {
            float vv = ib[(size_t)c * 625 + p];
#pragma unroll
            for (int o = 0; o < COUT_; o++) acc[o] = fmaf(vv, wsm[o * HID_ + c], acc[o]);
        }
#pragma unroll
        for (int o = 0; o < COUT_; o++) ob[(size_t)o * 625 + p] = acc[o];
    }
}

// ---------------------------------------------------------------------------
extern "C" void kernel_launch(void* const* d_in, const int* in_sizes, int n_in,
                              void* d_out, int out_size) {
    const float* kernel_in = (const float*)d_in[0];
    const float* search_in = (const float*)d_in[1];
    const float* wk  = (const float*)d_in[2];
    const float* bnk = (const float*)d_in[3];
    const float* ws  = (const float*)d_in[4];
    const float* bns = (const float*)d_in[5];
    const float* wd  = (const float*)d_in[6];
    const float* bnd = (const float*)d_in[7];
    const float* wh1 = (const float*)d_in[8];
    const float* bnh = (const float*)d_in[9];
    const float* wh2 = (const float*)d_in[10];
    const float* bh2 = (const float*)d_in[11];
    float* out = (float*)d_out;

    float *kfeat, *sfeat, *h;
    uint32_t *wkh, *wkl, *wsh, *wsl, *wdh, *wdl, *wh1h, *wh1l;
    uint32_t *kinh, *kinl, *sinh, *sinl, *fph, *fpl, *f2h, *f2l;
    cudaGetSymbolAddress((void**)&kfeat, g_kfeat);
    cudaGetSymbolAddress((void**)&sfeat, g_sfeat);
    cudaGetSymbolAddress((void**)&h,     g_h);
    cudaGetSymbolAddress((void**)&wkh, g_wk_hi);  cudaGetSymbolAddress((void**)&wkl, g_wk_lo);
    cudaGetSymbolAddress((void**)&wsh, g_ws_hi);  cudaGetSymbolAddress((void**)&wsl, g_ws_lo);
    cudaGetSymbolAddress((void**)&wdh, g_wd_hi);  cudaGetSymbolAddress((void**)&wdl, g_wd_lo);
    cudaGetSymbolAddress((void**)&wh1h, g_wh1_hi); cudaGetSymbolAddress((void**)&wh1l, g_wh1_lo);
    cudaGetSymbolAddress((void**)&kinh, g_kin_hi); cudaGetSymbolAddress((void**)&kinl, g_kin_lo);
    cudaGetSymbolAddress((void**)&sinh, g_sin_hi); cudaGetSymbolAddress((void**)&sinl, g_sin_lo);
    cudaGetSymbolAddress((void**)&fph, g_featP_hi); cudaGetSymbolAddress((void**)&fpl, g_featP_lo);
    cudaGetSymbolAddress((void**)&f2h, g_f2P_hi);  cudaGetSymbolAddress((void**)&f2l, g_f2P_lo);

    constexpr int SMEM = 8 * 128 * 20 * 4;  // 81920

    cudaFuncSetAttribute(gemm_mma2_kernel<0, 7, 7, 2304, true, 0>,
                         cudaFuncAttributeMaxDynamicSharedMemorySize, SMEM);
    cudaFuncSetAttribute(gemm_mma2_kernel<0, 31, 31, 2304, true, 0>,
                         cudaFuncAttributeMaxDynamicSharedMemorySize, SMEM);
    cudaFuncSetAttribute(gemm_mma2_kernel<1, 3, 3, 768, false, 1>,
                         cudaFuncAttributeMaxDynamicSharedMemorySize, SMEM);
    cudaFuncSetAttribute(gemm_mma2_kernel<1, 3, 3, 256, true, 0>,
                         cudaFuncAttributeMaxDynamicSharedMemorySize, SMEM);

    prep_in<961><<<(128 * 64 * 961 + 255) / 256, 256>>>(search_in, sinh, sinl);
    prep_w3<<<(9 * 256 * 128 + 255) / 256, 256>>>(ws, wsh, wsl);
    prep_w3<<<(9 * 256 * 128 + 255) / 256, 256>>>(wk, wkh, wkl);
    prep_w1<768><<<(256 * 384 + 255) / 256, 256>>>(wd, wdh, wdl);
    prep_w1<256><<<(256 * 128 + 255) / 256, 256>>>(wh1, wh1h, wh1l);
    prep_in<49><<<(128 * 64 * 49 + 255) / 256, 256>>>(kernel_in, kinh, kinl);

    // search branch conv3x3 -> g_sfeat ; NP=53824 -> 421 pixel tiles
    gemm_mma2_kernel<0, 31, 31, 2304, true, 0><<<dim3(2, 421), 256, SMEM>>>(
        sinh, sinl, wsh, wsl, bns, sfeat, nullptr, nullptr);
    // kernel branch conv3x3 -> g_kfeat ; NP=1600 -> 13 pixel tiles
    gemm_mma2_kernel<0, 7, 7, 2304, true, 0><<<dim3(2, 13), 256, SMEM>>>(
        kinh, kinl, wkh, wkl, bnk, kfeat, nullptr, nullptr);
    // xcorr -> packed featP (paired channels, u32 stores)
    multixcorr_kernel<<<dim3(128, B_), 256>>>(sfeat, kfeat, fph, fpl);
    // wd + bn -> packed f2P ; 313 pixel tiles
    gemm_mma2_kernel<1, 3, 3, 768, false, 1><<<dim3(2, 313), 256, SMEM>>>(
        fph, fpl, wdh, wdl, bnd, nullptr, (uint16_t*)f2h, (uint16_t*)f2l);
    // wh1 + bn + relu -> g_h
    gemm_mma2_kernel<1, 3, 3, 256, true, 0><<<dim3(2, 313), 256, SMEM>>>(
        f2h, f2l, wh1h, wh1l, bnh, h, nullptr, nullptr);
    // wh2 + bias -> out
    conv1x1_out_kernel<<<dim3(B_, 5), 128>>>(h, wh2, bh2, out);
}

// round 10
// speedup vs baseline: 1.1664x; 1.0179x over previous
#include <cuda_runtime.h>
#include <cuda_bf16.h>
#include <math.h>
#include <stdint.h>

#define B_    64
#define CIN_  256
#define HID_  256
#define COUT_ 10
#define EPS_  1e-5f

// ---------------------------------------------------------------------------
// Device globals (no runtime allocation allowed)
// ---------------------------------------------------------------------------
__device__ float g_kfeat[B_ * HID_ * 25];        // (64,256,5,5)
__device__ float g_sfeat[B_ * HID_ * 841];       // (64,256,29,29)
__device__ float g_h    [B_ * HID_ * 625];       // (64,256,25,25)
// packed bf16 hi/lo weights, smem-ready order
__device__ __align__(16) uint32_t g_wk_hi[9 * 256 * 128], g_wk_lo[9 * 256 * 128];
__device__ __align__(16) uint32_t g_ws_hi[9 * 256 * 128], g_ws_lo[9 * 256 * 128];
__device__ __align__(16) uint32_t g_wd_hi[256 * 384],     g_wd_lo[256 * 384];
__device__ __align__(16) uint32_t g_wh1_hi[256 * 128],    g_wh1_lo[256 * 128];
// packed bf16 hi/lo inputs: [icpair 128][b 64][HW]
__device__ __align__(16) uint32_t g_kin_hi[128 * 64 * 49],  g_kin_lo[128 * 64 * 49];
__device__ __align__(16) uint32_t g_sin_hi[128 * 64 * 961], g_sin_lo[128 * 64 * 961];
// packed bf16 hi/lo activations: [kpair][n=40000]
__device__ __align__(16) uint32_t g_featP_hi[384 * 40000], g_featP_lo[384 * 40000];
__device__ __align__(16) uint32_t g_f2P_hi [128 * 40000], g_f2P_lo [128 * 40000];

// ---------------------------------------------------------------------------
// PTX helpers (baseline ISA only; compiles for plain compute_103)
// ---------------------------------------------------------------------------
__device__ __forceinline__ void mma_bf16(float* c, const uint32_t* a,
                                         const uint32_t* b) {
    asm volatile(
        "mma.sync.aligned.m16n8k16.row.col.f32.bf16.bf16.f32 "
        "{%0,%1,%2,%3}, {%4,%5,%6,%7}, {%8,%9}, {%0,%1,%2,%3};"
        : "+f"(c[0]), "+f"(c[1]), "+f"(c[2]), "+f"(c[3])
        : "r"(a[0]), "r"(a[1]), "r"(a[2]), "r"(a[3]), "r"(b[0]), "r"(b[1]));
}

__device__ __forceinline__ void ldm4(uint32_t* d, uint32_t addr) {
    asm volatile("ldmatrix.sync.aligned.m8n8.x4.shared.b16 {%0,%1,%2,%3}, [%4];"
                 : "=r"(d[0]), "=r"(d[1]), "=r"(d[2]), "=r"(d[3]) : "r"(addr));
}

__device__ __forceinline__ uint32_t smem_u32(const void* p) {
    uint32_t a;
    asm("{ .reg .u64 t; cvta.to.shared.u64 t, %1; cvt.u32.u64 %0, t; }"
        : "=r"(a) : "l"(p));
    return a;
}

#define CP_ASYNC16(dst, src) \
    asm volatile("cp.async.cg.shared.global [%0], [%1], 16;" :: "r"(dst), "l"(src))
#define CP_COMMIT()  asm volatile("cp.async.commit_group;")
#define CP_WAIT0()   asm volatile("cp.async.wait_group 0;" ::: "memory")

__device__ __forceinline__ void split2(float a, float b, uint32_t& hi, uint32_t& lo) {
    __nv_bfloat162 h = __floats2bfloat162_rn(a, b);
    hi = *reinterpret_cast<uint32_t*>(&h);
    float ra = a - __bfloat162float(h.x);
    float rb = b - __bfloat162float(h.y);
    __nv_bfloat162 l = __floats2bfloat162_rn(ra, rb);
    lo = *reinterpret_cast<uint32_t*>(&l);
}

__device__ __forceinline__ void split1_u16(float v, uint16_t& hi, uint16_t& lo) {
    __nv_bfloat16 h = __float2bfloat16_rn(v);
    hi = *reinterpret_cast<uint16_t*>(&h);
    float r = v - __bfloat162float(h);
    __nv_bfloat16 l = __float2bfloat16_rn(r);
    lo = *reinterpret_cast<uint16_t*>(&l);
}

// pack two bf16-hi (and two bf16-lo) of (a,b) into u32 words
__device__ __forceinline__ void split2w(float a, float b, uint32_t& hw, uint32_t& lw) {
    uint16_t ha, la, hb, lb;
    split1_u16(a, ha, la);
    split1_u16(b, hb, lb);
    hw = (uint32_t)ha | ((uint32_t)hb << 16);
    lw = (uint32_t)la | ((uint32_t)lb << 16);
}

// ---------------------------------------------------------------------------
// Prep kernels
// ---------------------------------------------------------------------------
__global__ void prep_w3(const float* __restrict__ w,
                        uint32_t* __restrict__ oh, uint32_t* __restrict__ ol) {
    int idx = blockIdx.x * 256 + threadIdx.x;
    if (idx >= 9 * 256 * 128) return;
    int tap = idx >> 15;
    int rem = idx & 32767;
    int oc = rem >> 7, p = rem & 127;
    float a = w[(size_t)oc * 2304 + (2 * p) * 9 + tap];
    float b = w[(size_t)oc * 2304 + (2 * p + 1) * 9 + tap];
    split2(a, b, oh[idx], ol[idx]);
}

template <int K>
__global__ void prep_w1(const float* __restrict__ w,
                        uint32_t* __restrict__ oh, uint32_t* __restrict__ ol) {
    int idx = blockIdx.x * 256 + threadIdx.x;
    if (idx >= 256 * (K / 2)) return;
    int oc = idx / (K / 2), kp = idx - oc * (K / 2);
    split2(w[(size_t)oc * K + 2 * kp], w[(size_t)oc * K + 2 * kp + 1],
           oh[idx], ol[idx]);
}

template <int HW>
__global__ void prep_in(const float* __restrict__ in,
                        uint32_t* __restrict__ oh, uint32_t* __restrict__ ol) {
    int idx = blockIdx.x * 256 + threadIdx.x;
    if (idx >= 128 * 64 * HW) return;
    int p = idx / (64 * HW);
    int rem = idx - p * (64 * HW);
    int b = rem / HW, pix = rem - b * HW;
    const float* src = in + (size_t)b * 256 * HW + (2 * p) * HW + pix;
    split2(src[0], src[HW], oh[idx], ol[idx]);
}

// ---------------------------------------------------------------------------
// Tensor-core GEMM (bf16x3): C[oc][n] = sum_k A[oc][k]*B[k][n], + BN (+ReLU)
// MODE 0: implicit-GEMM 3x3 conv (k = tap*256+ic). MODE 1: 1x1 conv.
// EPI 0: fp32 NCHW. EPI 1: packed bf16 hi/lo [kpair][n].
// R5-proven config: tile M=128 x N=128 x K=32/stage, RSTR=20, double-buffered,
// late-issue stageA, grid (pixel tiles, 2 oc halves), 2 CTAs/SM.
// ---------------------------------------------------------------------------
template <int MODE, int HIN, int WIN, int KT, bool RELU, int EPI>
__global__ void __launch_bounds__(256, 2)
gemm_mma2_kernel(const uint32_t* __restrict__ bH_src, const uint32_t* __restrict__ bL_src,
                 const uint32_t* __restrict__ aH_src, const uint32_t* __restrict__ aL_src,
                 const float* __restrict__ bn, float* __restrict__ out,
                 uint16_t* __restrict__ outH, uint16_t* __restrict__ outL) {
    constexpr int WOUT = WIN - 2;
    constexpr int PXB  = (MODE == 0) ? (HIN - 2) * WOUT : 625;
    constexpr int NP   = 64 * PXB;
    constexpr int HW   = HIN * WIN;
    constexpr int S    = KT / 32;
    constexpr int RSTR = 20;
    constexpr int TILE = 128 * RSTR;
    constexpr int AR   = (MODE == 0) ? 128 : (KT / 2);
    constexpr int PLSTR = 64 * HW;

    extern __shared__ uint32_t smem[];
    const uint32_t smb = smem_u32(smem);

    const int tid  = threadIdx.x;
    const int warp = tid >> 5;
    const int lane = tid & 31;
    const int gid  = lane >> 2;
    const int tig  = lane & 3;
    const int moff = (warp >> 1) * 32;
    const int noff = (warp & 1) * 64;

    const int oc0 = blockIdx.y * 128;
    const int p0  = blockIdx.x * 128;

    const int aRow = lane & 15;
    const int aCol = (lane >> 4) * 4;
    const int bRow = (lane & 7) + ((lane >> 4) & 1) * 8;
    const int bCol = ((lane >> 3) & 1) * 4;

    const int nloc  = tid & 127;
    const int nglob = p0 + nloc;
    const bool nvalid = (nglob < NP);
    int bbase = 0;
    if (MODE == 0) {
        int nn = nvalid ? nglob : 0;
        int b = nn / PXB; int rem = nn - b * PXB;
        int y = rem / WOUT; int x = rem - y * WOUT;
        bbase = b * HW + y * WIN + x;
    }

    float acc[2][8][4];
#pragma unroll
    for (int a = 0; a < 2; a++)
#pragma unroll
        for (int b = 0; b < 8; b++)
#pragma unroll
            for (int c = 0; c < 4; c++) acc[a][b][c] = 0.f;

    auto prefetchB = [&](int s, uint32_t v[4][4]) {
        int tapoff = 0, plane0 = 0;
        if (MODE == 0) {
            int tap = s >> 3; plane0 = (s & 7) * 16;
            tapoff = (tap / 3) * WIN + (tap % 3);
        }
#pragma unroll
        for (int i = 0; i < 4; i++) {
            int task = tid + 256 * i;
            int hl = task >> 9;
            int wg = (task >> 7) & 3;
            const uint32_t* src = hl ? bL_src : bH_src;
#pragma unroll
            for (int j = 0; j < 4; j++) {
                int w = wg * 4 + j;
                long addr = (MODE == 0)
                    ? (long)(plane0 + w) * PLSTR + bbase + tapoff
                    : (long)(s * 16 + w) * 40000 + nglob;
                v[i][j] = nvalid ? __ldg(src + addr) : 0u;
            }
        }
    };
    auto storeB = [&](int buf, uint32_t v[4][4]) {
#pragma unroll
        for (int i = 0; i < 4; i++) {
            int task = tid + 256 * i;
            int hl = task >> 9;
            int wg = (task >> 7) & 3;
            uint32_t* dst = &smem[(buf * 4 + 2 + hl) * TILE + nloc * RSTR + wg * 4];
            *reinterpret_cast<uint4*>(dst) =
                make_uint4(v[i][0], v[i][1], v[i][2], v[i][3]);
        }
    };
    auto stageA = [&](int buf, int s) {
        int abase;
        if (MODE == 0) {
            int tap = s >> 3; int plane0 = (s & 7) * 16;
            abase = tap * 32768 + oc0 * 128 + plane0;
        } else {
            abase = oc0 * (KT / 2) + s * 16;
        }
#pragma unroll
        for (int i = 0; i < 4; i++) {
            int task = tid + 256 * i;
            int hl = task >> 9;
            int rem = task & 511;
            int r = rem >> 2;
            int c = (rem & 3) * 4;
            const uint32_t* src = (hl ? aL_src : aH_src) + abase + r * AR + c;
            uint32_t dst = smb + ((buf * 4 + hl) * TILE + r * RSTR + c) * 4;
            CP_ASYNC16(dst, src);
        }
    };

    // prologue: fill buf 0
    {
        uint32_t v[4][4];
        prefetchB(0, v);
        storeB(0, v);
        stageA(0, 0);
        CP_COMMIT();
    }

    for (int s = 0; s < S; s++) {
        const int buf = s & 1;
        CP_WAIT0();
        __syncthreads();

        const bool have = (s + 1 < S);
        uint32_t vpre[4][4];
        if (have) prefetchB(s + 1, vpre);

        const uint32_t smA_hi = smb + (buf * 4 + 0) * TILE * 4;
        const uint32_t smA_lo = smb + (buf * 4 + 1) * TILE * 4;
        const uint32_t smB_hi = smb + (buf * 4 + 2) * TILE * 4;
        const uint32_t smB_lo = smb + (buf * 4 + 3) * TILE * 4;
#pragma unroll
        for (int kc = 0; kc < 2; kc++) {
            uint32_t aH[2][4], aL[2][4];
#pragma unroll
            for (int mf = 0; mf < 2; mf++) {
                uint32_t off = ((moff + mf * 16 + aRow) * RSTR + kc * 8 + aCol) * 4;
                ldm4(aH[mf], smA_hi + off);
                ldm4(aL[mf], smA_lo + off);
            }
#pragma unroll
            for (int nfp = 0; nfp < 4; nfp++) {
                uint32_t boff = ((noff + nfp * 16 + bRow) * RSTR + kc * 8 + bCol) * 4;
                uint32_t bHf[4], bLf[4];
                ldm4(bHf, smB_hi + boff);
                ldm4(bLf, smB_lo + boff);
#pragma unroll
                for (int snf = 0; snf < 2; snf++) {
                    int nf = nfp * 2 + snf;
#pragma unroll
                    for (int mf = 0; mf < 2; mf++) {
                        mma_bf16(acc[mf][nf], aH[mf], &bHf[2 * snf]);
                        mma_bf16(acc[mf][nf], aH[mf], &bLf[2 * snf]);
                        mma_bf16(acc[mf][nf], aL[mf], &bHf[2 * snf]);
                    }
                }
            }
        }

        if (have) {
            storeB(buf ^ 1, vpre);
            stageA(buf ^ 1, s + 1);   // late issue (R5-proven order)
            CP_COMMIT();
        }
    }

    // epilogue
    __syncthreads();
    float* Cs = (float*)smem;                // 128 x 132 fp32 (67584 B)
#pragma unroll
    for (int mf = 0; mf < 2; mf++) {
#pragma unroll
        for (int nf = 0; nf < 8; nf++) {
            int m0 = moff + mf * 16 + gid;
            int nl = noff + nf * 8 + 2 * tig;
            *(float2*)&Cs[m0 * 132 + nl]       = make_float2(acc[mf][nf][0], acc[mf][nf][1]);
            *(float2*)&Cs[(m0 + 8) * 132 + nl] = make_float2(acc[mf][nf][2], acc[mf][nf][3]);
        }
    }
    __syncthreads();

    for (int t = warp; t < 128; t += 8) {
        const int oc = oc0 + t;
        const float g  = bn[oc];
        const float be = bn[256 + oc];
        const float mm = bn[512 + oc];
        const float vv = bn[768 + oc];
        const float inv  = g * rsqrtf(vv + EPS_);
        const float bias = be - mm * inv;
#pragma unroll
        for (int cc0 = 0; cc0 < 128; cc0 += 32) {
            int cc = cc0 + lane;
            int n = p0 + cc;
            if (n < NP) {
                float val = Cs[t * 132 + cc] * inv + bias;
                if (RELU) val = fmaxf(val, 0.f);
                if (EPI == 0) {
                    int b = n / PXB; int rq = n - b * PXB;
                    out[((size_t)(b * 256 + oc)) * PXB + rq] = val;
                } else {
                    uint16_t h, l;
                    split1_u16(val, h, l);
                    size_t off = (size_t)(oc >> 1) * 80000 + n * 2 + (oc & 1);
                    outH[off] = h;
                    outL[off] = l;
                }
            }
        }
    }
}

// ---------------------------------------------------------------------------
// Multi-scale depthwise xcorr, paired channels: block = (kp0, b) handles
// channels 2*kp0 and 2*kp0+1, emitting full u32 packed words (coalesced).
// ---------------------------------------------------------------------------
__global__ void multixcorr_kernel(const float* __restrict__ s,
                                  const float* __restrict__ k,
                                  uint32_t* __restrict__ fh,
                                  uint32_t* __restrict__ fl) {
    const int kp0 = blockIdx.x;   // 0..127
    const int b   = blockIdx.y;

    __shared__ float ss[2][841];
    __shared__ float kk[2][25];

    const float* sp = s + ((size_t)b * HID_ + 2 * kp0) * 841;
    const float* kp = k + ((size_t)b * HID_ + 2 * kp0) * 25;

    for (int i = threadIdx.x; i < 2 * 841; i += blockDim.x)
        ss[i / 841][i % 841] = sp[i];
    if (threadIdx.x < 50) kk[threadIdx.x / 25][threadIdx.x % 25] = kp[threadIdx.x];
    __syncthreads();

    for (int p = threadIdx.x; p < 625; p += blockDim.x) {
        const int y = p / 25, x = p - (p / 25) * 25;
        float f0[2], f1[2], f2[2];
#pragma unroll
        for (int h = 0; h < 2; h++) {
            float s_full = 0.f, s_in = 0.f;
#pragma unroll
            for (int dy = 0; dy < 5; dy++)
#pragma unroll
                for (int dx = 0; dx < 5; dx++) {
                    float vv = ss[h][(y + dy) * 29 + (x + dx)] * kk[h][dy * 5 + dx];
                    s_full += vv;
                    if (dy >= 1 && dy <= 3 && dx >= 1 && dx <= 3) s_in += vv;
                }
            f0[h] = s_full;
            f1[h] = s_in;
            f2[h] = ss[h][(y + 2) * 29 + (x + 2)] * kk[h][12];
        }
        const int n = b * 625 + p;
        uint32_t hw, lw;
        split2w(f0[0], f0[1], hw, lw);
        fh[(size_t)kp0 * 40000 + n] = hw;
        fl[(size_t)kp0 * 40000 + n] = lw;
        split2w(f1[0], f1[1], hw, lw);
        fh[(size_t)(128 + kp0) * 40000 + n] = hw;
        fl[(size_t)(128 + kp0) * 40000 + n] = lw;
        split2w(f2[0], f2[1], hw, lw);
        fh[(size_t)(256 + kp0) * 40000 + n] = hw;
        fl[(size_t)(256 + kp0) * 40000 + n] = lw;
    }
}

// ---------------------------------------------------------------------------
// Final 1x1: (B,256,625) x (10,256) + bias -> (B,10,625). grid (B, 5).
// ---------------------------------------------------------------------------
__global__ void conv1x1_out_kernel(const float* __restrict__ in,
                                   const float* __restrict__ w,
                                   const float* __restrict__ bias,
                                   float* __restrict__ out) {
    const int b = blockIdx.x;
    const int chunk = blockIdx.y;

    __shared__ float wsm[COUT_ * HID_];
    for (int i = threadIdx.x; i < COUT_ * HID_; i += blockDim.x) wsm[i] = w[i];
    __syncthreads();

    const float* ib = in + (size_t)b * HID_ * 625;
    float* ob = out + (size_t)b * COUT_ * 625;

    const int pend = min(625, (chunk + 1) * 125);
    for (int p = chunk * 125 + threadIdx.x; p < pend; p += blockDim.x) {
        float acc[COUT_];
#pragma unroll
        for (int o = 0; o < COUT_; o++) acc[o] = bias[o];
        for (int c = 0; c < HID_; c++) {
            float vv = ib[(size_t)c * 625 + p];
#pragma unroll
            for (int o = 0; o < COUT_; o++) acc[o] = fmaf(vv, wsm[o * HID_ + c], acc[o]);
        }
#pragma unroll
        for (int o = 0; o < COUT_; o++) ob[(size_t)o * 625 + p] = acc[o];
    }
}

// ---------------------------------------------------------------------------
extern "C" void kernel_launch(void* const* d_in, const int* in_sizes, int n_in,
                              void* d_out, int out_size) {
    const float* kernel_in = (const float*)d_in[0];
    const float* search_in = (const float*)d_in[1];
    const float* wk  = (const float*)d_in[2];
    const float* bnk = (const float*)d_in[3];
    const float* ws  = (const float*)d_in[4];
    const float* bns = (const float*)d_in[5];
    const float* wd  = (const float*)d_in[6];
    const float* bnd = (const float*)d_in[7];
    const float* wh1 = (const float*)d_in[8];
    const float* bnh = (const float*)d_in[9];
    const float* wh2 = (const float*)d_in[10];
    const float* bh2 = (const float*)d_in[11];
    float* out = (float*)d_out;

    float *kfeat, *sfeat, *h;
    uint32_t *wkh, *wkl, *wsh, *wsl, *wdh, *wdl, *wh1h, *wh1l;
    uint32_t *kinh, *kinl, *sinh, *sinl, *fph, *fpl, *f2h, *f2l;
    cudaGetSymbolAddress((void**)&kfeat, g_kfeat);
    cudaGetSymbolAddress((void**)&sfeat, g_sfeat);
    cudaGetSymbolAddress((void**)&h,     g_h);
    cudaGetSymbolAddress((void**)&wkh, g_wk_hi);  cudaGetSymbolAddress((void**)&wkl, g_wk_lo);
    cudaGetSymbolAddress((void**)&wsh, g_ws_hi);  cudaGetSymbolAddress((void**)&wsl, g_ws_lo);
    cudaGetSymbolAddress((void**)&wdh, g_wd_hi);  cudaGetSymbolAddress((void**)&wdl, g_wd_lo);
    cudaGetSymbolAddress((void**)&wh1h, g_wh1_hi); cudaGetSymbolAddress((void**)&wh1l, g_wh1_lo);
    cudaGetSymbolAddress((void**)&kinh, g_kin_hi); cudaGetSymbolAddress((void**)&kinl, g_kin_lo);
    cudaGetSymbolAddress((void**)&sinh, g_sin_hi); cudaGetSymbolAddress((void**)&sinl, g_sin_lo);
    cudaGetSymbolAddress((void**)&fph, g_featP_hi); cudaGetSymbolAddress((void**)&fpl, g_featP_lo);
    cudaGetSymbolAddress((void**)&f2h, g_f2P_hi);  cudaGetSymbolAddress((void**)&f2l, g_f2P_lo);

    constexpr int SMEM = 8 * 128 * 20 * 4;  // 81920

    cudaFuncSetAttribute(gemm_mma2_kernel<0, 7, 7, 2304, true, 0>,
                         cudaFuncAttributeMaxDynamicSharedMemorySize, SMEM);
    cudaFuncSetAttribute(gemm_mma2_kernel<0, 31, 31, 2304, true, 0>,
                         cudaFuncAttributeMaxDynamicSharedMemorySize, SMEM);
    cudaFuncSetAttribute(gemm_mma2_kernel<1, 3, 3, 768, false, 1>,
                         cudaFuncAttributeMaxDynamicSharedMemorySize, SMEM);
    cudaFuncSetAttribute(gemm_mma2_kernel<1, 3, 3, 256, true, 0>,
                         cudaFuncAttributeMaxDynamicSharedMemorySize, SMEM);

    // #0-#2: dependencies of gemm_s + one filler (window = launch index 3)
    prep_in<961><<<(128 * 64 * 961 + 255) / 256, 256>>>(search_in, sinh, sinl); // 0
    prep_w3<<<(9 * 256 * 128 + 255) / 256, 256>>>(ws, wsh, wsl);                // 1
    prep_w1<768><<<(256 * 384 + 255) / 256, 256>>>(wd, wdh, wdl);               // 2

    // #3: search branch conv3x3 -> g_sfeat ; NP=53824 -> 421 tiles  [PROFILED]
    gemm_mma2_kernel<0, 31, 31, 2304, true, 0><<<dim3(421, 2), 256, SMEM>>>(
        sinh, sinl, wsh, wsl, bns, sfeat, nullptr, nullptr);

    // remaining preps
    prep_w3<<<(9 * 256 * 128 + 255) / 256, 256>>>(wk, wkh, wkl);                // 4
    prep_w1<256><<<(256 * 128 + 255) / 256, 256>>>(wh1, wh1h, wh1l);            // 5
    prep_in<49><<<(128 * 64 * 49 + 255) / 256, 256>>>(kernel_in, kinh, kinl);   // 6

    // kernel branch conv3x3 -> g_kfeat ; NP=1600 -> 13 tiles
    gemm_mma2_kernel<0, 7, 7, 2304, true, 0><<<dim3(13, 2), 256, SMEM>>>(
        kinh, kinl, wkh, wkl, bnk, kfeat, nullptr, nullptr);
    // xcorr -> packed featP (paired channels, u32 stores)
    multixcorr_kernel<<<dim3(128, B_), 256>>>(sfeat, kfeat, fph, fpl);
    // wd + bn -> packed f2P ; 313 tiles
    gemm_mma2_kernel<1, 3, 3, 768, false, 1><<<dim3(313, 2), 256, SMEM>>>(
        fph, fpl, wdh, wdl, bnd, nullptr, (uint16_t*)f2h, (uint16_t*)f2l);
    // wh1 + bn + relu -> g_h
    gemm_mma2_kernel<1, 3, 3, 256, true, 0><<<dim3(313, 2), 256, SMEM>>>(
        f2h, f2l, wh1h, wh1l, bnh, h, nullptr, nullptr);
    // wh2 + bias -> out
    conv1x1_out_kernel<<<dim3(B_, 5), 128>>>(h, wh2, bh2, out);
}

// round 11
// speedup vs baseline: 1.3828x; 1.1855x over previous
#include <cuda_runtime.h>
#include <cuda_bf16.h>
#include <cuda_fp16.h>
#include <math.h>
#include <stdint.h>

#define B_    64
#define CIN_  256
#define HID_  256
#define COUT_ 10
#define EPS_  1e-5f

// ---------------------------------------------------------------------------
// Device globals (no runtime allocation allowed)
// ---------------------------------------------------------------------------
__device__ float g_kfeat[B_ * HID_ * 25];        // (64,256,5,5)
__device__ float g_sfeat[B_ * HID_ * 841];       // (64,256,29,29)
__device__ float g_h    [B_ * HID_ * 625];       // (64,256,25,25)
// bf16 packed hi/lo weights (conv_k, wd, wh1)
__device__ __align__(16) uint32_t g_wk_hi[9 * 256 * 128], g_wk_lo[9 * 256 * 128];
__device__ __align__(16) uint32_t g_wd_hi[256 * 384],     g_wd_lo[256 * 384];
__device__ __align__(16) uint32_t g_wh1_hi[256 * 128],    g_wh1_lo[256 * 128];
// fp16 packed hi/lo weights (conv_s)
__device__ __align__(16) uint32_t g_ws_hi16[9 * 256 * 128], g_ws_lo16[9 * 256 * 128];
// bf16 packed hi/lo kernel input: [icpair 128][b 64][49]
__device__ __align__(16) uint32_t g_kin_hi[128 * 64 * 49],  g_kin_lo[128 * 64 * 49];
// fp16 packed (single) search input: [icpair 128][b 64][961]
__device__ __align__(16) uint32_t g_sinF[128 * 64 * 961];
// bf16 packed hi/lo activations: [kpair][n=40000]
__device__ __align__(16) uint32_t g_featP_hi[384 * 40000], g_featP_lo[384 * 40000];
__device__ __align__(16) uint32_t g_f2P_hi [128 * 40000], g_f2P_lo [128 * 40000];

// ---------------------------------------------------------------------------
// PTX helpers (baseline ISA only; compiles for plain compute_103)
// ---------------------------------------------------------------------------
__device__ __forceinline__ void mma_bf16(float* c, const uint32_t* a,
                                         const uint32_t* b) {
    asm volatile(
        "mma.sync.aligned.m16n8k16.row.col.f32.bf16.bf16.f32 "
        "{%0,%1,%2,%3}, {%4,%5,%6,%7}, {%8,%9}, {%0,%1,%2,%3};"
        : "+f"(c[0]), "+f"(c[1]), "+f"(c[2]), "+f"(c[3])
        : "r"(a[0]), "r"(a[1]), "r"(a[2]), "r"(a[3]), "r"(b[0]), "r"(b[1]));
}

__device__ __forceinline__ void mma_f16(float* c, const uint32_t* a,
                                        const uint32_t* b) {
    asm volatile(
        "mma.sync.aligned.m16n8k16.row.col.f32.f16.f16.f32 "
        "{%0,%1,%2,%3}, {%4,%5,%6,%7}, {%8,%9}, {%0,%1,%2,%3};"
        : "+f"(c[0]), "+f"(c[1]), "+f"(c[2]), "+f"(c[3])
        : "r"(a[0]), "r"(a[1]), "r"(a[2]), "r"(a[3]), "r"(b[0]), "r"(b[1]));
}

__device__ __forceinline__ void ldm4(uint32_t* d, uint32_t addr) {
    asm volatile("ldmatrix.sync.aligned.m8n8.x4.shared.b16 {%0,%1,%2,%3}, [%4];"
                 : "=r"(d[0]), "=r"(d[1]), "=r"(d[2]), "=r"(d[3]) : "r"(addr));
}

__device__ __forceinline__ uint32_t smem_u32(const void* p) {
    uint32_t a;
    asm("{ .reg .u64 t; cvta.to.shared.u64 t, %1; cvt.u32.u64 %0, t; }"
        : "=r"(a) : "l"(p));
    return a;
}

#define CP_ASYNC16(dst, src) \
    asm volatile("cp.async.cg.shared.global [%0], [%1], 16;" :: "r"(dst), "l"(src))
#define CP_COMMIT()  asm volatile("cp.async.commit_group;")
#define CP_WAIT0()   asm volatile("cp.async.wait_group 0;" ::: "memory")

__device__ __forceinline__ void split2(float a, float b, uint32_t& hi, uint32_t& lo) {
    __nv_bfloat162 h = __floats2bfloat162_rn(a, b);
    hi = *reinterpret_cast<uint32_t*>(&h);
    float ra = a - __bfloat162float(h.x);
    float rb = b - __bfloat162float(h.y);
    __nv_bfloat162 l = __floats2bfloat162_rn(ra, rb);
    lo = *reinterpret_cast<uint32_t*>(&l);
}

__device__ __forceinline__ void split2h(float a, float b, uint32_t& hi, uint32_t& lo) {
    __half ha = __float2half_rn(a), hb = __float2half_rn(b);
    __half la = __float2half_rn(a - __half2float(ha));
    __half lb = __float2half_rn(b - __half2float(hb));
    __half2 H = __halves2half2(ha, hb), L = __halves2half2(la, lb);
    hi = *reinterpret_cast<uint32_t*>(&H);
    lo = *reinterpret_cast<uint32_t*>(&L);
}

__device__ __forceinline__ uint32_t pack2h(float a, float b) {
    __half2 H = __floats2half2_rn(a, b);
    return *reinterpret_cast<uint32_t*>(&H);
}

__device__ __forceinline__ void split1_u16(float v, uint16_t& hi, uint16_t& lo) {
    __nv_bfloat16 h = __float2bfloat16_rn(v);
    hi = *reinterpret_cast<uint16_t*>(&h);
    float r = v - __bfloat162float(h);
    __nv_bfloat16 l = __float2bfloat16_rn(r);
    lo = *reinterpret_cast<uint16_t*>(&l);
}

__device__ __forceinline__ void split2w(float a, float b, uint32_t& hw, uint32_t& lw) {
    uint16_t ha, la, hb, lb;
    split1_u16(a, ha, la);
    split1_u16(b, hb, lb);
    hw = (uint32_t)ha | ((uint32_t)hb << 16);
    lw = (uint32_t)la | ((uint32_t)lb << 16);
}

// ---------------------------------------------------------------------------
// Prep kernels
// ---------------------------------------------------------------------------
__global__ void prep_w3(const float* __restrict__ w,
                        uint32_t* __restrict__ oh, uint32_t* __restrict__ ol) {
    int idx = blockIdx.x * 256 + threadIdx.x;
    if (idx >= 9 * 256 * 128) return;
    int tap = idx >> 15;
    int rem = idx & 32767;
    int oc = rem >> 7, p = rem & 127;
    float a = w[(size_t)oc * 2304 + (2 * p) * 9 + tap];
    float b = w[(size_t)oc * 2304 + (2 * p + 1) * 9 + tap];
    split2(a, b, oh[idx], ol[idx]);
}

__global__ void prep_w3_f16(const float* __restrict__ w,
                            uint32_t* __restrict__ oh, uint32_t* __restrict__ ol) {
    int idx = blockIdx.x * 256 + threadIdx.x;
    if (idx >= 9 * 256 * 128) return;
    int tap = idx >> 15;
    int rem = idx & 32767;
    int oc = rem >> 7, p = rem & 127;
    float a = w[(size_t)oc * 2304 + (2 * p) * 9 + tap];
    float b = w[(size_t)oc * 2304 + (2 * p + 1) * 9 + tap];
    split2h(a, b, oh[idx], ol[idx]);
}

template <int K>
__global__ void prep_w1(const float* __restrict__ w,
                        uint32_t* __restrict__ oh, uint32_t* __restrict__ ol) {
    int idx = blockIdx.x * 256 + threadIdx.x;
    if (idx >= 256 * (K / 2)) return;
    int oc = idx / (K / 2), kp = idx - oc * (K / 2);
    split2(w[(size_t)oc * K + 2 * kp], w[(size_t)oc * K + 2 * kp + 1],
           oh[idx], ol[idx]);
}

template <int HW>
__global__ void prep_in(const float* __restrict__ in,
                        uint32_t* __restrict__ oh, uint32_t* __restrict__ ol) {
    int idx = blockIdx.x * 256 + threadIdx.x;
    if (idx >= 128 * 64 * HW) return;
    int p = idx / (64 * HW);
    int rem = idx - p * (64 * HW);
    int b = rem / HW, pix = rem - b * HW;
    const float* src = in + (size_t)b * 256 * HW + (2 * p) * HW + pix;
    split2(src[0], src[HW], oh[idx], ol[idx]);
}

template <int HW>
__global__ void prep_in_f16(const float* __restrict__ in,
                            uint32_t* __restrict__ of) {
    int idx = blockIdx.x * 256 + threadIdx.x;
    if (idx >= 128 * 64 * HW) return;
    int p = idx / (64 * HW);
    int rem = idx - p * (64 * HW);
    int b = rem / HW, pix = rem - b * HW;
    const float* src = in + (size_t)b * 256 * HW + (2 * p) * HW + pix;
    of[idx] = pack2h(src[0], src[HW]);
}

// ---------------------------------------------------------------------------
// Tensor-core GEMM: C[oc][n] = sum_k A[oc][k]*B[k][n], + BN (+ReLU)
// MODE 0: implicit-GEMM 3x3 conv (k = tap*256+ic). MODE 1: 1x1 conv.
// EPI 0: fp32 NCHW. EPI 1: packed bf16 hi/lo [kpair][n].
// PREC 0: bf16x3 (A hi/lo x B hi/lo, 3 mma). PREC 1: fp16x2 (A hi/lo exact,
//         B single fp16, 2 mma — error = B fp16 quantization only).
// R5-proven config otherwise: M=128 x N=128 x K=32/stage, RSTR=20,
// double-buffered, late-issue stageA, 2 CTAs/SM.
// ---------------------------------------------------------------------------
template <int MODE, int HIN, int WIN, int KT, bool RELU, int EPI, int PREC>
__global__ void __launch_bounds__(256, 2)
gemm_mma2_kernel(const uint32_t* __restrict__ bH_src, const uint32_t* __restrict__ bL_src,
                 const uint32_t* __restrict__ aH_src, const uint32_t* __restrict__ aL_src,
                 const float* __restrict__ bn, float* __restrict__ out,
                 uint16_t* __restrict__ outH, uint16_t* __restrict__ outL) {
    constexpr int WOUT = WIN - 2;
    constexpr int PXB  = (MODE == 0) ? (HIN - 2) * WOUT : 625;
    constexpr int NP   = 64 * PXB;
    constexpr int HW   = HIN * WIN;
    constexpr int S    = KT / 32;
    constexpr int RSTR = 20;
    constexpr int TILE = 128 * RSTR;
    constexpr int TPB  = PREC ? 3 : 4;       // tiles per buffer
    constexpr int NBT  = PREC ? 2 : 4;       // B prefetch tasks per thread
    constexpr int AR   = (MODE == 0) ? 128 : (KT / 2);
    constexpr int PLSTR = 64 * HW;

    extern __shared__ uint32_t smem[];
    const uint32_t smb = smem_u32(smem);

    const int tid  = threadIdx.x;
    const int warp = tid >> 5;
    const int lane = tid & 31;
    const int gid  = lane >> 2;
    const int tig  = lane & 3;
    const int moff = (warp >> 1) * 32;
    const int noff = (warp & 1) * 64;

    const int oc0 = blockIdx.y * 128;
    const int p0  = blockIdx.x * 128;

    const int aRow = lane & 15;
    const int aCol = (lane >> 4) * 4;
    const int bRow = (lane & 7) + ((lane >> 4) & 1) * 8;
    const int bCol = ((lane >> 3) & 1) * 4;

    const int nloc  = tid & 127;
    const int nglob = p0 + nloc;
    const bool nvalid = (nglob < NP);
    int bbase = 0;
    if (MODE == 0) {
        int nn = nvalid ? nglob : 0;
        int b = nn / PXB; int rem = nn - b * PXB;
        int y = rem / WOUT; int x = rem - y * WOUT;
        bbase = b * HW + y * WIN + x;
    }

    float acc[2][8][4];
#pragma unroll
    for (int a = 0; a < 2; a++)
#pragma unroll
        for (int b = 0; b < 8; b++)
#pragma unroll
            for (int c = 0; c < 4; c++) acc[a][b][c] = 0.f;

    auto prefetchB = [&](int s, uint32_t v[NBT][4]) {
        int tapoff = 0, plane0 = 0;
        if (MODE == 0) {
            int tap = s >> 3; plane0 = (s & 7) * 16;
            tapoff = (tap / 3) * WIN + (tap % 3);
        }
#pragma unroll
        for (int i = 0; i < NBT; i++) {
            int task = tid + 256 * i;
            int hl = PREC ? 0 : (task >> 9);
            int wg = (task >> 7) & 3;
            const uint32_t* src = hl ? bL_src : bH_src;
#pragma unroll
            for (int j = 0; j < 4; j++) {
                int w = wg * 4 + j;
                long addr = (MODE == 0)
                    ? (long)(plane0 + w) * PLSTR + bbase + tapoff
                    : (long)(s * 16 + w) * 40000 + nglob;
                v[i][j] = nvalid ? __ldg(src + addr) : 0u;
            }
        }
    };
    auto storeB = [&](int buf, uint32_t v[NBT][4]) {
#pragma unroll
        for (int i = 0; i < NBT; i++) {
            int task = tid + 256 * i;
            int hl = PREC ? 0 : (task >> 9);
            int wg = (task >> 7) & 3;
            uint32_t* dst = &smem[(buf * TPB + 2 + hl) * TILE + nloc * RSTR + wg * 4];
            *reinterpret_cast<uint4*>(dst) =
                make_uint4(v[i][0], v[i][1], v[i][2], v[i][3]);
        }
    };
    auto stageA = [&](int buf, int s) {
        int abase;
        if (MODE == 0) {
            int tap = s >> 3; int plane0 = (s & 7) * 16;
            abase = tap * 32768 + oc0 * 128 + plane0;
        } else {
            abase = oc0 * (KT / 2) + s * 16;
        }
#pragma unroll
        for (int i = 0; i < 4; i++) {
            int task = tid + 256 * i;
            int hl = task >> 9;
            int rem = task & 511;
            int r = rem >> 2;
            int c = (rem & 3) * 4;
            const uint32_t* src = (hl ? aL_src : aH_src) + abase + r * AR + c;
            uint32_t dst = smb + ((buf * TPB + hl) * TILE + r * RSTR + c) * 4;
            CP_ASYNC16(dst, src);
        }
    };

    // prologue: fill buf 0
    {
        uint32_t v[NBT][4];
        prefetchB(0, v);
        storeB(0, v);
        stageA(0, 0);
        CP_COMMIT();
    }

    for (int s = 0; s < S; s++) {
        const int buf = s & 1;
        CP_WAIT0();
        __syncthreads();

        const bool have = (s + 1 < S);
        uint32_t vpre[NBT][4];
        if (have) prefetchB(s + 1, vpre);

        const uint32_t smA_hi = smb + (buf * TPB + 0) * TILE * 4;
        const uint32_t smA_lo = smb + (buf * TPB + 1) * TILE * 4;
        const uint32_t smB_hi = smb + (buf * TPB + 2) * TILE * 4;
        const uint32_t smB_lo = PREC ? smB_hi : (smb + (buf * TPB + 3) * TILE * 4);
#pragma unroll
        for (int kc = 0; kc < 2; kc++) {
            uint32_t aH[2][4], aL[2][4];
#pragma unroll
            for (int mf = 0; mf < 2; mf++) {
                uint32_t off = ((moff + mf * 16 + aRow) * RSTR + kc * 8 + aCol) * 4;
                ldm4(aH[mf], smA_hi + off);
                ldm4(aL[mf], smA_lo + off);
            }
#pragma unroll
            for (int nfp = 0; nfp < 4; nfp++) {
                uint32_t boff = ((noff + nfp * 16 + bRow) * RSTR + kc * 8 + bCol) * 4;
                uint32_t bHf[4], bLf[4];
                ldm4(bHf, smB_hi + boff);
                if (!PREC) ldm4(bLf, smB_lo + boff);
#pragma unroll
                for (int snf = 0; snf < 2; snf++) {
                    int nf = nfp * 2 + snf;
#pragma unroll
                    for (int mf = 0; mf < 2; mf++) {
                        if (PREC) {
                            mma_f16(acc[mf][nf], aH[mf], &bHf[2 * snf]);
                            mma_f16(acc[mf][nf], aL[mf], &bHf[2 * snf]);
                        } else {
                            mma_bf16(acc[mf][nf], aH[mf], &bHf[2 * snf]);
                            mma_bf16(acc[mf][nf], aH[mf], &bLf[2 * snf]);
                            mma_bf16(acc[mf][nf], aL[mf], &bHf[2 * snf]);
                        }
                    }
                }
            }
        }

        if (have) {
            storeB(buf ^ 1, vpre);
            stageA(buf ^ 1, s + 1);   // late issue (R5-proven order)
            CP_COMMIT();
        }
    }

    // epilogue
    __syncthreads();
    float* Cs = (float*)smem;                // 128 x 132 fp32 (67584 B)
#pragma unroll
    for (int mf = 0; mf < 2; mf++) {
#pragma unroll
        for (int nf = 0; nf < 8; nf++) {
            int m0 = moff + mf * 16 + gid;
            int nl = noff + nf * 8 + 2 * tig;
            *(float2*)&Cs[m0 * 132 + nl]       = make_float2(acc[mf][nf][0], acc[mf][nf][1]);
            *(float2*)&Cs[(m0 + 8) * 132 + nl] = make_float2(acc[mf][nf][2], acc[mf][nf][3]);
        }
    }
    __syncthreads();

    for (int t = warp; t < 128; t += 8) {
        const int oc = oc0 + t;
        const float g  = bn[oc];
        const float be = bn[256 + oc];
        const float mm = bn[512 + oc];
        const float vv = bn[768 + oc];
        const float inv  = g * rsqrtf(vv + EPS_);
        const float bias = be - mm * inv;
#pragma unroll
        for (int cc0 = 0; cc0 < 128; cc0 += 32) {
            int cc = cc0 + lane;
            int n = p0 + cc;
            if (n < NP) {
                float val = Cs[t * 132 + cc] * inv + bias;
                if (RELU) val = fmaxf(val, 0.f);
                if (EPI == 0) {
                    int b = n / PXB; int rq = n - b * PXB;
                    out[((size_t)(b * 256 + oc)) * PXB + rq] = val;
                } else {
                    uint16_t h, l;
                    split1_u16(val, h, l);
                    size_t off = (size_t)(oc >> 1) * 80000 + n * 2 + (oc & 1);
                    outH[off] = h;
                    outL[off] = l;
                }
            }
        }
    }
}

// ---------------------------------------------------------------------------
// Multi-scale depthwise xcorr, paired channels, u32 packed stores.
// ---------------------------------------------------------------------------
__global__ void multixcorr_kernel(const float* __restrict__ s,
                                  const float* __restrict__ k,
                                  uint32_t* __restrict__ fh,
                                  uint32_t* __restrict__ fl) {
    const int kp0 = blockIdx.x;   // 0..127
    const int b   = blockIdx.y;

    __shared__ float ss[2][841];
    __shared__ float kk[2][25];

    const float* sp = s + ((size_t)b * HID_ + 2 * kp0) * 841;
    const float* kp = k + ((size_t)b * HID_ + 2 * kp0) * 25;

    for (int i = threadIdx.x; i < 2 * 841; i += blockDim.x)
        ss[i / 841][i % 841] = sp[i];
    if (threadIdx.x < 50) kk[threadIdx.x / 25][threadIdx.x % 25] = kp[threadIdx.x];
    __syncthreads();

    for (int p = threadIdx.x; p < 625; p += blockDim.x) {
        const int y = p / 25, x = p - (p / 25) * 25;
        float f0[2], f1[2], f2[2];
#pragma unroll
        for (int h = 0; h < 2; h++) {
            float s_full = 0.f, s_in = 0.f;
#pragma unroll
            for (int dy = 0; dy < 5; dy++)
#pragma unroll
                for (int dx = 0; dx < 5; dx++) {
                    float vv = ss[h][(y + dy) * 29 + (x + dx)] * kk[h][dy * 5 + dx];
                    s_full += vv;
                    if (dy >= 1 && dy <= 3 && dx >= 1 && dx <= 3) s_in += vv;
                }
            f0[h] = s_full;
            f1[h] = s_in;
            f2[h] = ss[h][(y + 2) * 29 + (x + 2)] * kk[h][12];
        }
        const int n = b * 625 + p;
        uint32_t hw, lw;
        split2w(f0[0], f0[1], hw, lw);
        fh[(size_t)kp0 * 40000 + n] = hw;
        fl[(size_t)kp0 * 40000 + n] = lw;
        split2w(f1[0], f1[1], hw, lw);
        fh[(size_t)(128 + kp0) * 40000 + n] = hw;
        fl[(size_t)(128 + kp0) * 40000 + n] = lw;
        split2w(f2[0], f2[1], hw, lw);
        fh[(size_t)(256 + kp0) * 40000 + n] = hw;
        fl[(size_t)(256 + kp0) * 40000 + n] = lw;
    }
}

// ---------------------------------------------------------------------------
// Final 1x1: (B,256,625) x (10,256) + bias -> (B,10,625). grid (B, 5).
// ---------------------------------------------------------------------------
__global__ void conv1x1_out_kernel(const float* __restrict__ in,
                                   const float* __restrict__ w,
                                   const float* __restrict__ bias,
                                   float* __restrict__ out) {
    const int b = blockIdx.x;
    const int chunk = blockIdx.y;

    __shared__ float wsm[COUT_ * HID_];
    for (int i = threadIdx.x; i < COUT_ * HID_; i += blockDim.x) wsm[i] = w[i];
    __syncthreads();

    const float* ib = in + (size_t)b * HID_ * 625;
    float* ob = out + (size_t)b * COUT_ * 625;

    const int pend = min(625, (chunk + 1) * 125);
    for (int p = chunk * 125 + threadIdx.x; p < pend; p += blockDim.x) {
        float acc[COUT_];
#pragma unroll
        for (int o = 0; o < COUT_; o++) acc[o] = bias[o];
        for (int c = 0; c < HID_; c++) {
            float vv = ib[(size_t)c * 625 + p];
#pragma unroll
            for (int o = 0; o < COUT_; o++) acc[o] = fmaf(vv, wsm[o * HID_ + c], acc[o]);
        }
#pragma unroll
        for (int o = 0; o < COUT_; o++) ob[(size_t)o * 625 + p] = acc[o];
    }
}

// ---------------------------------------------------------------------------
extern "C" void kernel_launch(void* const* d_in, const int* in_sizes, int n_in,
                              void* d_out, int out_size) {
    const float* kernel_in = (const float*)d_in[0];
    const float* search_in = (const float*)d_in[1];
    const float* wk  = (const float*)d_in[2];
    const float* bnk = (const float*)d_in[3];
    const float* ws  = (const float*)d_in[4];
    const float* bns = (const float*)d_in[5];
    const float* wd  = (const float*)d_in[6];
    const float* bnd = (const float*)d_in[7];
    const float* wh1 = (const float*)d_in[8];
    const float* bnh = (const float*)d_in[9];
    const float* wh2 = (const float*)d_in[10];
    const float* bh2 = (const float*)d_in[11];
    float* out = (float*)d_out;

    float *kfeat, *sfeat, *h;
    uint32_t *wkh, *wkl, *wdh, *wdl, *wh1h, *wh1l;
    uint32_t *wsh16, *wsl16, *sinF;
    uint32_t *kinh, *kinl, *fph, *fpl, *f2h, *f2l;
    cudaGetSymbolAddress((void**)&kfeat, g_kfeat);
    cudaGetSymbolAddress((void**)&sfeat, g_sfeat);
    cudaGetSymbolAddress((void**)&h,     g_h);
    cudaGetSymbolAddress((void**)&wkh, g_wk_hi);  cudaGetSymbolAddress((void**)&wkl, g_wk_lo);
    cudaGetSymbolAddress((void**)&wdh, g_wd_hi);  cudaGetSymbolAddress((void**)&wdl, g_wd_lo);
    cudaGetSymbolAddress((void**)&wh1h, g_wh1_hi); cudaGetSymbolAddress((void**)&wh1l, g_wh1_lo);
    cudaGetSymbolAddress((void**)&wsh16, g_ws_hi16); cudaGetSymbolAddress((void**)&wsl16, g_ws_lo16);
    cudaGetSymbolAddress((void**)&sinF, g_sinF);
    cudaGetSymbolAddress((void**)&kinh, g_kin_hi); cudaGetSymbolAddress((void**)&kinl, g_kin_lo);
    cudaGetSymbolAddress((void**)&fph, g_featP_hi); cudaGetSymbolAddress((void**)&fpl, g_featP_lo);
    cudaGetSymbolAddress((void**)&f2h, g_f2P_hi);  cudaGetSymbolAddress((void**)&f2l, g_f2P_lo);

    constexpr int SMEM0 = 8 * 128 * 20 * 4;   // 81920 (bf16x3: 4 tiles x 2 bufs)
    constexpr int SMEM1 = 128 * 132 * 4;      // 67584 (fp16x2: 3x2 tiles = 61440 < epi)

    cudaFuncSetAttribute(gemm_mma2_kernel<0, 7, 7, 2304, true, 0, 0>,
                         cudaFuncAttributeMaxDynamicSharedMemorySize, SMEM0);
    cudaFuncSetAttribute(gemm_mma2_kernel<0, 31, 31, 2304, true, 0, 1>,
                         cudaFuncAttributeMaxDynamicSharedMemorySize, SMEM1);
    cudaFuncSetAttribute(gemm_mma2_kernel<1, 3, 3, 768, false, 1, 0>,
                         cudaFuncAttributeMaxDynamicSharedMemorySize, SMEM0);
    cudaFuncSetAttribute(gemm_mma2_kernel<1, 3, 3, 256, true, 0, 0>,
                         cudaFuncAttributeMaxDynamicSharedMemorySize, SMEM0);

    // #0-#2: dependencies of gemm_s + filler (ncu window = launch index 3)
    prep_in_f16<961><<<(128 * 64 * 961 + 255) / 256, 256>>>(search_in, sinF);   // 0
    prep_w3_f16<<<(9 * 256 * 128 + 255) / 256, 256>>>(ws, wsh16, wsl16);        // 1
    prep_w1<768><<<(256 * 384 + 255) / 256, 256>>>(wd, wdh, wdl);               // 2

    // #3: search branch conv3x3 (fp16 2-mma) -> g_sfeat  [PROFILED]
    gemm_mma2_kernel<0, 31, 31, 2304, true, 0, 1><<<dim3(421, 2), 256, SMEM1>>>(
        sinF, nullptr, wsh16, wsl16, bns, sfeat, nullptr, nullptr);

    // remaining preps
    prep_w3<<<(9 * 256 * 128 + 255) / 256, 256>>>(wk, wkh, wkl);                // 4
    prep_w1<256><<<(256 * 128 + 255) / 256, 256>>>(wh1, wh1h, wh1l);            // 5
    prep_in<49><<<(128 * 64 * 49 + 255) / 256, 256>>>(kernel_in, kinh, kinl);   // 6

    // kernel branch conv3x3 (bf16x3) -> g_kfeat ; NP=1600 -> 13 tiles
    gemm_mma2_kernel<0, 7, 7, 2304, true, 0, 0><<<dim3(13, 2), 256, SMEM0>>>(
        kinh, kinl, wkh, wkl, bnk, kfeat, nullptr, nullptr);
    // xcorr -> packed featP
    multixcorr_kernel<<<dim3(128, B_), 256>>>(sfeat, kfeat, fph, fpl);
    // wd + bn -> packed f2P ; 313 tiles
    gemm_mma2_kernel<1, 3, 3, 768, false, 1, 0><<<dim3(313, 2), 256, SMEM0>>>(
        fph, fpl, wdh, wdl, bnd, nullptr, (uint16_t*)f2h, (uint16_t*)f2l);
    // wh1 + bn + relu -> g_h
    gemm_mma2_kernel<1, 3, 3, 256, true, 0, 0><<<dim3(313, 2), 256, SMEM0>>>(
        f2h, f2l, wh1h, wh1l, bnh, h, nullptr, nullptr);
    // wh2 + bias -> out
    conv1x1_out_kernel<<<dim3(B_, 5), 128>>>(h, wh2, bh2, out);
}

// round 12
// speedup vs baseline: 1.5847x; 1.1461x over previous
#include <cuda_runtime.h>
#include <cuda_fp16.h>
#include <math.h>
#include <stdint.h>

#define B_    64
#define CIN_  256
#define HID_  256
#define COUT_ 10
#define EPS_  1e-5f

// ---------------------------------------------------------------------------
// Device globals (no runtime allocation allowed)
// ---------------------------------------------------------------------------
__device__ float g_kfeat[B_ * HID_ * 25];        // (64,256,5,5)
__device__ float g_sfeat[B_ * HID_ * 841];       // (64,256,29,29)
__device__ float g_h    [B_ * HID_ * 625];       // (64,256,25,25)
// fp16 packed hi/lo weights (exact split: hi + lo reproduces fp32 to ~2^-22)
__device__ __align__(16) uint32_t g_wk_hi[9 * 256 * 128], g_wk_lo[9 * 256 * 128];
__device__ __align__(16) uint32_t g_ws_hi[9 * 256 * 128], g_ws_lo[9 * 256 * 128];
__device__ __align__(16) uint32_t g_wd_hi[256 * 384],     g_wd_lo[256 * 384];
__device__ __align__(16) uint32_t g_wh1_hi[256 * 128],    g_wh1_lo[256 * 128];
// fp16 packed (single) inputs: [icpair 128][b 64][HW]
__device__ __align__(16) uint32_t g_kinF[128 * 64 * 49];
__device__ __align__(16) uint32_t g_sinF[128 * 64 * 961];
// fp16 packed (single) activations: [kpair][n=40000]
__device__ __align__(16) uint32_t g_featF[384 * 40000];
__device__ __align__(16) uint32_t g_f2F [128 * 40000];

// ---------------------------------------------------------------------------
// PTX helpers (baseline ISA only; compiles for plain compute_103)
// ---------------------------------------------------------------------------
__device__ __forceinline__ void mma_f16(float* c, const uint32_t* a,
                                        const uint32_t* b) {
    asm volatile(
        "mma.sync.aligned.m16n8k16.row.col.f32.f16.f16.f32 "
        "{%0,%1,%2,%3}, {%4,%5,%6,%7}, {%8,%9}, {%0,%1,%2,%3};"
        : "+f"(c[0]), "+f"(c[1]), "+f"(c[2]), "+f"(c[3])
        : "r"(a[0]), "r"(a[1]), "r"(a[2]), "r"(a[3]), "r"(b[0]), "r"(b[1]));
}

__device__ __forceinline__ void ldm4(uint32_t* d, uint32_t addr) {
    asm volatile("ldmatrix.sync.aligned.m8n8.x4.shared.b16 {%0,%1,%2,%3}, [%4];"
                 : "=r"(d[0]), "=r"(d[1]), "=r"(d[2]), "=r"(d[3]) : "r"(addr));
}

__device__ __forceinline__ uint32_t smem_u32(const void* p) {
    uint32_t a;
    asm("{ .reg .u64 t; cvta.to.shared.u64 t, %1; cvt.u32.u64 %0, t; }"
        : "=r"(a) : "l"(p));
    return a;
}

#define CP_ASYNC16(dst, src) \
    asm volatile("cp.async.cg.shared.global [%0], [%1], 16;" :: "r"(dst), "l"(src))
#define CP_COMMIT()  asm volatile("cp.async.commit_group;")
#define CP_WAIT0()   asm volatile("cp.async.wait_group 0;" ::: "memory")

__device__ __forceinline__ void split2h(float a, float b, uint32_t& hi, uint32_t& lo) {
    __half ha = __float2half_rn(a), hb = __float2half_rn(b);
    __half la = __float2half_rn(a - __half2float(ha));
    __half lb = __float2half_rn(b - __half2float(hb));
    __half2 H = __halves2half2(ha, hb), L = __halves2half2(la, lb);
    hi = *reinterpret_cast<uint32_t*>(&H);
    lo = *reinterpret_cast<uint32_t*>(&L);
}

__device__ __forceinline__ uint32_t pack2h(float a, float b) {
    __half2 H = __floats2half2_rn(a, b);
    return *reinterpret_cast<uint32_t*>(&H);
}

// ---------------------------------------------------------------------------
// Prep kernels
// ---------------------------------------------------------------------------
__global__ void prep_w3_f16(const float* __restrict__ w,
                            uint32_t* __restrict__ oh, uint32_t* __restrict__ ol) {
    int idx = blockIdx.x * 256 + threadIdx.x;
    if (idx >= 9 * 256 * 128) return;
    int tap = idx >> 15;
    int rem = idx & 32767;
    int oc = rem >> 7, p = rem & 127;
    float a = w[(size_t)oc * 2304 + (2 * p) * 9 + tap];
    float b = w[(size_t)oc * 2304 + (2 * p + 1) * 9 + tap];
    split2h(a, b, oh[idx], ol[idx]);
}

template <int K>
__global__ void prep_w1_f16(const float* __restrict__ w,
                            uint32_t* __restrict__ oh, uint32_t* __restrict__ ol) {
    int idx = blockIdx.x * 256 + threadIdx.x;
    if (idx >= 256 * (K / 2)) return;
    int oc = idx / (K / 2), kp = idx - oc * (K / 2);
    split2h(w[(size_t)oc * K + 2 * kp], w[(size_t)oc * K + 2 * kp + 1],
            oh[idx], ol[idx]);
}

template <int HW>
__global__ void prep_in_f16(const float* __restrict__ in,
                            uint32_t* __restrict__ of) {
    int idx = blockIdx.x * 256 + threadIdx.x;
    if (idx >= 128 * 64 * HW) return;
    int p = idx / (64 * HW);
    int rem = idx - p * (64 * HW);
    int b = rem / HW, pix = rem - b * HW;
    const float* src = in + (size_t)b * 256 * HW + (2 * p) * HW + pix;
    of[idx] = pack2h(src[0], src[HW]);
}

// ---------------------------------------------------------------------------
// Tensor-core GEMM (fp16x2): C[oc][n] = sum_k A[oc][k]*B[k][n], + BN (+ReLU)
// A = weights split fp16 hi+lo (exact), B single fp16 -> 2 mma per fragment;
// error = B quantization only (~2^-11 RMS relative).
// MODE 0: implicit-GEMM 3x3 conv (k = tap*256+ic). MODE 1: 1x1 conv.
// EPI 0: fp32 NCHW. EPI 1: packed fp16 [kpair][n].
// R5-proven schedule: M=128 x N=128 x K=32/stage, RSTR=20, double-buffered,
// late-issue stageA, 2 CTAs/SM.
// ---------------------------------------------------------------------------
template <int MODE, int HIN, int WIN, int KT, bool RELU, int EPI>
__global__ void __launch_bounds__(256, 2)
gemm_f16_kernel(const uint32_t* __restrict__ bF_src,
                const uint32_t* __restrict__ aH_src, const uint32_t* __restrict__ aL_src,
                const float* __restrict__ bn, float* __restrict__ out,
                uint16_t* __restrict__ outF) {
    constexpr int WOUT = WIN - 2;
    constexpr int PXB  = (MODE == 0) ? (HIN - 2) * WOUT : 625;
    constexpr int NP   = 64 * PXB;
    constexpr int HW   = HIN * WIN;
    constexpr int S    = KT / 32;
    constexpr int RSTR = 20;
    constexpr int TILE = 128 * RSTR;
    constexpr int TPB  = 3;                  // A_hi, A_lo, B per buffer
    constexpr int AR   = (MODE == 0) ? 128 : (KT / 2);
    constexpr int PLSTR = 64 * HW;

    extern __shared__ uint32_t smem[];
    const uint32_t smb = smem_u32(smem);

    const int tid  = threadIdx.x;
    const int warp = tid >> 5;
    const int lane = tid & 31;
    const int gid  = lane >> 2;
    const int tig  = lane & 3;
    const int moff = (warp >> 1) * 32;
    const int noff = (warp & 1) * 64;

    const int oc0 = blockIdx.y * 128;
    const int p0  = blockIdx.x * 128;

    const int aRow = lane & 15;
    const int aCol = (lane >> 4) * 4;
    const int bRow = (lane & 7) + ((lane >> 4) & 1) * 8;
    const int bCol = ((lane >> 3) & 1) * 4;

    const int nloc  = tid & 127;
    const int nglob = p0 + nloc;
    const bool nvalid = (nglob < NP);
    int bbase = 0;
    if (MODE == 0) {
        int nn = nvalid ? nglob : 0;
        int b = nn / PXB; int rem = nn - b * PXB;
        int y = rem / WOUT; int x = rem - y * WOUT;
        bbase = b * HW + y * WIN + x;
    }

    float acc[2][8][4];
#pragma unroll
    for (int a = 0; a < 2; a++)
#pragma unroll
        for (int b = 0; b < 8; b++)
#pragma unroll
            for (int c = 0; c < 4; c++) acc[a][b][c] = 0.f;

    auto prefetchB = [&](int s, uint32_t v[2][4]) {
        int tapoff = 0, plane0 = 0;
        if (MODE == 0) {
            int tap = s >> 3; plane0 = (s & 7) * 16;
            tapoff = (tap / 3) * WIN + (tap % 3);
        }
#pragma unroll
        for (int i = 0; i < 2; i++) {
            int task = tid + 256 * i;
            int wg = (task >> 7) & 3;
#pragma unroll
            for (int j = 0; j < 4; j++) {
                int w = wg * 4 + j;
                long addr = (MODE == 0)
                    ? (long)(plane0 + w) * PLSTR + bbase + tapoff
                    : (long)(s * 16 + w) * 40000 + nglob;
                v[i][j] = nvalid ? __ldg(bF_src + addr) : 0u;
            }
        }
    };
    auto storeB = [&](int buf, uint32_t v[2][4]) {
#pragma unroll
        for (int i = 0; i < 2; i++) {
            int task = tid + 256 * i;
            int wg = (task >> 7) & 3;
            uint32_t* dst = &smem[(buf * TPB + 2) * TILE + nloc * RSTR + wg * 4];
            *reinterpret_cast<uint4*>(dst) =
                make_uint4(v[i][0], v[i][1], v[i][2], v[i][3]);
        }
    };
    auto stageA = [&](int buf, int s) {
        int abase;
        if (MODE == 0) {
            int tap = s >> 3; int plane0 = (s & 7) * 16;
            abase = tap * 32768 + oc0 * 128 + plane0;
        } else {
            abase = oc0 * (KT / 2) + s * 16;
        }
#pragma unroll
        for (int i = 0; i < 4; i++) {
            int task = tid + 256 * i;
            int hl = task >> 9;
            int rem = task & 511;
            int r = rem >> 2;
            int c = (rem & 3) * 4;
            const uint32_t* src = (hl ? aL_src : aH_src) + abase + r * AR + c;
            uint32_t dst = smb + ((buf * TPB + hl) * TILE + r * RSTR + c) * 4;
            CP_ASYNC16(dst, src);
        }
    };

    // prologue: fill buf 0
    {
        uint32_t v[2][4];
        prefetchB(0, v);
        storeB(0, v);
        stageA(0, 0);
        CP_COMMIT();
    }

    for (int s = 0; s < S; s++) {
        const int buf = s & 1;
        CP_WAIT0();
        __syncthreads();

        const bool have = (s + 1 < S);
        uint32_t vpre[2][4];
        if (have) prefetchB(s + 1, vpre);

        const uint32_t smA_hi = smb + (buf * TPB + 0) * TILE * 4;
        const uint32_t smA_lo = smb + (buf * TPB + 1) * TILE * 4;
        const uint32_t smB    = smb + (buf * TPB + 2) * TILE * 4;
#pragma unroll
        for (int kc = 0; kc < 2; kc++) {
            uint32_t aH[2][4], aL[2][4];
#pragma unroll
            for (int mf = 0; mf < 2; mf++) {
                uint32_t off = ((moff + mf * 16 + aRow) * RSTR + kc * 8 + aCol) * 4;
                ldm4(aH[mf], smA_hi + off);
                ldm4(aL[mf], smA_lo + off);
            }
#pragma unroll
            for (int nfp = 0; nfp < 4; nfp++) {
                uint32_t boff = ((noff + nfp * 16 + bRow) * RSTR + kc * 8 + bCol) * 4;
                uint32_t bf[4];
                ldm4(bf, smB + boff);
#pragma unroll
                for (int snf = 0; snf < 2; snf++) {
                    int nf = nfp * 2 + snf;
#pragma unroll
                    for (int mf = 0; mf < 2; mf++) {
                        mma_f16(acc[mf][nf], aH[mf], &bf[2 * snf]);
                        mma_f16(acc[mf][nf], aL[mf], &bf[2 * snf]);
                    }
                }
            }
        }

        if (have) {
            storeB(buf ^ 1, vpre);
            stageA(buf ^ 1, s + 1);   // late issue (R5-proven order)
            CP_COMMIT();
        }
    }

    // epilogue
    __syncthreads();
    float* Cs = (float*)smem;                // 128 x 132 fp32 (67584 B)
#pragma unroll
    for (int mf = 0; mf < 2; mf++) {
#pragma unroll
        for (int nf = 0; nf < 8; nf++) {
            int m0 = moff + mf * 16 + gid;
            int nl = noff + nf * 8 + 2 * tig;
            *(float2*)&Cs[m0 * 132 + nl]       = make_float2(acc[mf][nf][0], acc[mf][nf][1]);
            *(float2*)&Cs[(m0 + 8) * 132 + nl] = make_float2(acc[mf][nf][2], acc[mf][nf][3]);
        }
    }
    __syncthreads();

    for (int t = warp; t < 128; t += 8) {
        const int oc = oc0 + t;
        const float g  = bn[oc];
        const float be = bn[256 + oc];
        const float mm = bn[512 + oc];
        const float vv = bn[768 + oc];
        const float inv  = g * rsqrtf(vv + EPS_);
        const float bias = be - mm * inv;
#pragma unroll
        for (int cc0 = 0; cc0 < 128; cc0 += 32) {
            int cc = cc0 + lane;
            int n = p0 + cc;
            if (n < NP) {
                float val = Cs[t * 132 + cc] * inv + bias;
                if (RELU) val = fmaxf(val, 0.f);
                if (EPI == 0) {
                    int b = n / PXB; int rq = n - b * PXB;
                    out[((size_t)(b * 256 + oc)) * PXB + rq] = val;
                } else {
                    __half hv = __float2half_rn(val);
                    outF[(size_t)(oc >> 1) * 80000 + n * 2 + (oc & 1)] =
                        *reinterpret_cast<uint16_t*>(&hv);
                }
            }
        }
    }
}

// ---------------------------------------------------------------------------
// Multi-scale depthwise xcorr, paired channels, single fp16 packed output.
// ---------------------------------------------------------------------------
__global__ void multixcorr_kernel(const float* __restrict__ s,
                                  const float* __restrict__ k,
                                  uint32_t* __restrict__ ff) {
    const int kp0 = blockIdx.x;   // 0..127
    const int b   = blockIdx.y;

    __shared__ float ss[2][841];
    __shared__ float kk[2][25];

    const float* sp = s + ((size_t)b * HID_ + 2 * kp0) * 841;
    const float* kp = k + ((size_t)b * HID_ + 2 * kp0) * 25;

    for (int i = threadIdx.x; i < 2 * 841; i += blockDim.x)
        ss[i / 841][i % 841] = sp[i];
    if (threadIdx.x < 50) kk[threadIdx.x / 25][threadIdx.x % 25] = kp[threadIdx.x];
    __syncthreads();

    for (int p = threadIdx.x; p < 625; p += blockDim.x) {
        const int y = p / 25, x = p - (p / 25) * 25;
        float f0[2], f1[2], f2[2];
#pragma unroll
        for (int h = 0; h < 2; h++) {
            float s_full = 0.f, s_in = 0.f;
#pragma unroll
            for (int dy = 0; dy < 5; dy++)
#pragma unroll
                for (int dx = 0; dx < 5; dx++) {
                    float vv = ss[h][(y + dy) * 29 + (x + dx)] * kk[h][dy * 5 + dx];
                    s_full += vv;
                    if (dy >= 1 && dy <= 3 && dx >= 1 && dx <= 3) s_in += vv;
                }
            f0[h] = s_full;
            f1[h] = s_in;
            f2[h] = ss[h][(y + 2) * 29 + (x + 2)] * kk[h][12];
        }
        const int n = b * 625 + p;
        ff[(size_t)kp0 * 40000 + n]         = pack2h(f0[0], f0[1]);
        ff[(size_t)(128 + kp0) * 40000 + n] = pack2h(f1[0], f1[1]);
        ff[(size_t)(256 + kp0) * 40000 + n] = pack2h(f2[0], f2[1]);
    }
}

// ---------------------------------------------------------------------------
// Final 1x1: (B,256,625) x (10,256) + bias -> (B,10,625). grid (B, 5).
// ---------------------------------------------------------------------------
__global__ void conv1x1_out_kernel(const float* __restrict__ in,
                                   const float* __restrict__ w,
                                   const float* __restrict__ bias,
                                   float* __restrict__ out) {
    const int b = blockIdx.x;
    const int chunk = blockIdx.y;

    __shared__ float wsm[COUT_ * HID_];
    for (int i = threadIdx.x; i < COUT_ * HID_; i += blockDim.x) wsm[i] = w[i];
    __syncthreads();

    const float* ib = in + (size_t)b * HID_ * 625;
    float* ob = out + (size_t)b * COUT_ * 625;

    const int pend = min(625, (chunk + 1) * 125);
    for (int p = chunk * 125 + threadIdx.x; p < pend; p += blockDim.x) {
        float acc[COUT_];
#pragma unroll
        for (int o = 0; o < COUT_; o++) acc[o] = bias[o];
        for (int c = 0; c < HID_; c++) {
            float vv = ib[(size_t)c * 625 + p];
#pragma unroll
            for (int o = 0; o < COUT_; o++) acc[o] = fmaf(vv, wsm[o * HID_ + c], acc[o]);
        }
#pragma unroll
        for (int o = 0; o < COUT_; o++) ob[(size_t)o * 625 + p] = acc[o];
    }
}

// ---------------------------------------------------------------------------
extern "C" void kernel_launch(void* const* d_in, const int* in_sizes, int n_in,
                              void* d_out, int out_size) {
    const float* kernel_in = (const float*)d_in[0];
    const float* search_in = (const float*)d_in[1];
    const float* wk  = (const float*)d_in[2];
    const float* bnk = (const float*)d_in[3];
    const float* ws  = (const float*)d_in[4];
    const float* bns = (const float*)d_in[5];
    const float* wd  = (const float*)d_in[6];
    const float* bnd = (const float*)d_in[7];
    const float* wh1 = (const float*)d_in[8];
    const float* bnh = (const float*)d_in[9];
    const float* wh2 = (const float*)d_in[10];
    const float* bh2 = (const float*)d_in[11];
    float* out = (float*)d_out;

    float *kfeat, *sfeat, *h;
    uint32_t *wkh, *wkl, *wsh, *wsl, *wdh, *wdl, *wh1h, *wh1l;
    uint32_t *kinF, *sinF, *featF, *f2F;
    cudaGetSymbolAddress((void**)&kfeat, g_kfeat);
    cudaGetSymbolAddress((void**)&sfeat, g_sfeat);
    cudaGetSymbolAddress((void**)&h,     g_h);
    cudaGetSymbolAddress((void**)&wkh, g_wk_hi);  cudaGetSymbolAddress((void**)&wkl, g_wk_lo);
    cudaGetSymbolAddress((void**)&wsh, g_ws_hi);  cudaGetSymbolAddress((void**)&wsl, g_ws_lo);
    cudaGetSymbolAddress((void**)&wdh, g_wd_hi);  cudaGetSymbolAddress((void**)&wdl, g_wd_lo);
    cudaGetSymbolAddress((void**)&wh1h, g_wh1_hi); cudaGetSymbolAddress((void**)&wh1l, g_wh1_lo);
    cudaGetSymbolAddress((void**)&kinF, g_kinF);
    cudaGetSymbolAddress((void**)&sinF, g_sinF);
    cudaGetSymbolAddress((void**)&featF, g_featF);
    cudaGetSymbolAddress((void**)&f2F, g_f2F);

    constexpr int SMEM = 128 * 132 * 4;   // 67584 (staging 3x2 tiles = 61440 < epi)

    cudaFuncSetAttribute(gemm_f16_kernel<0, 7, 7, 2304, true, 0>,
                         cudaFuncAttributeMaxDynamicSharedMemorySize, SMEM);
    cudaFuncSetAttribute(gemm_f16_kernel<0, 31, 31, 2304, true, 0>,
                         cudaFuncAttributeMaxDynamicSharedMemorySize, SMEM);
    cudaFuncSetAttribute(gemm_f16_kernel<1, 3, 3, 768, false, 1>,
                         cudaFuncAttributeMaxDynamicSharedMemorySize, SMEM);
    cudaFuncSetAttribute(gemm_f16_kernel<1, 3, 3, 256, true, 0>,
                         cudaFuncAttributeMaxDynamicSharedMemorySize, SMEM);

    // #0-#2: dependencies of gemm_s (ncu window = launch index 3)
    prep_in_f16<961><<<(128 * 64 * 961 + 255) / 256, 256>>>(search_in, sinF);   // 0
    prep_w3_f16<<<(9 * 256 * 128 + 255) / 256, 256>>>(ws, wsh, wsl);            // 1
    prep_w1_f16<768><<<(256 * 384 + 255) / 256, 256>>>(wd, wdh, wdl);           // 2

    // #3: search branch conv3x3 -> g_sfeat  [PROFILED]
    gemm_f16_kernel<0, 31, 31, 2304, true, 0><<<dim3(421, 2), 256, SMEM>>>(
        sinF, wsh, wsl, bns, sfeat, nullptr);

    // remaining preps
    prep_w3_f16<<<(9 * 256 * 128 + 255) / 256, 256>>>(wk, wkh, wkl);            // 4
    prep_w1_f16<256><<<(256 * 128 + 255) / 256, 256>>>(wh1, wh1h, wh1l);        // 5
    prep_in_f16<49><<<(128 * 64 * 49 + 255) / 256, 256>>>(kernel_in, kinF);     // 6

    // kernel branch conv3x3 -> g_kfeat
    gemm_f16_kernel<0, 7, 7, 2304, true, 0><<<dim3(13, 2), 256, SMEM>>>(
        kinF, wkh, wkl, bnk, kfeat, nullptr);
    // xcorr -> packed featF (single fp16)
    multixcorr_kernel<<<dim3(128, B_), 256>>>(sfeat, kfeat, featF);
    // wd + bn -> packed f2F
    gemm_f16_kernel<1, 3, 3, 768, false, 1><<<dim3(313, 2), 256, SMEM>>>(
        featF, wdh, wdl, bnd, nullptr, (uint16_t*)f2F);
    // wh1 + bn + relu -> g_h
    gemm_f16_kernel<1, 3, 3, 256, true, 0><<<dim3(313, 2), 256, SMEM>>>(
        f2F, wh1h, wh1l, bnh, h, nullptr);
    // wh2 + bias -> out
    conv1x1_out_kernel<<<dim3(B_, 5), 128>>>(h, wh2, bh2, out);
}

// round 13
// speedup vs baseline: 2.0534x; 1.2957x over previous
#include <cuda_runtime.h>
#include <cuda_fp16.h>
#include <math.h>
#include <stdint.h>

#define B_    64
#define CIN_  256
#define HID_  256
#define COUT_ 10
#define EPS_  1e-5f

// ---------------------------------------------------------------------------
// Device globals (no runtime allocation allowed)
// ---------------------------------------------------------------------------
__device__ float g_kfeat[B_ * HID_ * 25];        // (64,256,5,5)
__device__ float g_sfeat[B_ * HID_ * 841];       // (64,256,29,29)
__device__ float g_h    [B_ * HID_ * 625];       // (64,256,25,25)
// fp16 packed (single) weights, smem-ready order
__device__ __align__(16) uint32_t g_wk[9 * 256 * 128];
__device__ __align__(16) uint32_t g_ws[9 * 256 * 128];
__device__ __align__(16) uint32_t g_wd[256 * 384];
__device__ __align__(16) uint32_t g_wh1[256 * 128];
// fp16 packed (single) inputs: [icpair 128][b 64][HW]
__device__ __align__(16) uint32_t g_kinF[128 * 64 * 49];
__device__ __align__(16) uint32_t g_sinF[128 * 64 * 961];
// fp16 packed (single) activations: [kpair][n=40000]
__device__ __align__(16) uint32_t g_featF[384 * 40000];
__device__ __align__(16) uint32_t g_f2F [128 * 40000];

// ---------------------------------------------------------------------------
// PTX helpers (baseline ISA only; compiles for plain compute_103)
// ---------------------------------------------------------------------------
__device__ __forceinline__ void mma_f16(float* c, const uint32_t* a,
                                        const uint32_t* b) {
    asm volatile(
        "mma.sync.aligned.m16n8k16.row.col.f32.f16.f16.f32 "
        "{%0,%1,%2,%3}, {%4,%5,%6,%7}, {%8,%9}, {%0,%1,%2,%3};"
        : "+f"(c[0]), "+f"(c[1]), "+f"(c[2]), "+f"(c[3])
        : "r"(a[0]), "r"(a[1]), "r"(a[2]), "r"(a[3]), "r"(b[0]), "r"(b[1]));
}

__device__ __forceinline__ void ldm4(uint32_t* d, uint32_t addr) {
    asm volatile("ldmatrix.sync.aligned.m8n8.x4.shared.b16 {%0,%1,%2,%3}, [%4];"
                 : "=r"(d[0]), "=r"(d[1]), "=r"(d[2]), "=r"(d[3]) : "r"(addr));
}

__device__ __forceinline__ uint32_t smem_u32(const void* p) {
    uint32_t a;
    asm("{ .reg .u64 t; cvta.to.shared.u64 t, %1; cvt.u32.u64 %0, t; }"
        : "=r"(a) : "l"(p));
    return a;
}

#define CP_ASYNC16(dst, src) \
    asm volatile("cp.async.cg.shared.global [%0], [%1], 16;" :: "r"(dst), "l"(src))
#define CP_COMMIT()  asm volatile("cp.async.commit_group;")
#define CP_WAIT0()   asm volatile("cp.async.wait_group 0;" ::: "memory")

__device__ __forceinline__ uint32_t pack2h(float a, float b) {
    __half2 H = __floats2half2_rn(a, b);
    return *reinterpret_cast<uint32_t*>(&H);
}

// ---------------------------------------------------------------------------
// Prep kernels (single fp16)
// ---------------------------------------------------------------------------
__global__ void prep_w3_f16(const float* __restrict__ w,
                            uint32_t* __restrict__ of) {
    int idx = blockIdx.x * 256 + threadIdx.x;
    if (idx >= 9 * 256 * 128) return;
    int tap = idx >> 15;
    int rem = idx & 32767;
    int oc = rem >> 7, p = rem & 127;
    of[idx] = pack2h(w[(size_t)oc * 2304 + (2 * p) * 9 + tap],
                     w[(size_t)oc * 2304 + (2 * p + 1) * 9 + tap]);
}

template <int K>
__global__ void prep_w1_f16(const float* __restrict__ w,
                            uint32_t* __restrict__ of) {
    int idx = blockIdx.x * 256 + threadIdx.x;
    if (idx >= 256 * (K / 2)) return;
    int oc = idx / (K / 2), kp = idx - oc * (K / 2);
    of[idx] = pack2h(w[(size_t)oc * K + 2 * kp], w[(size_t)oc * K + 2 * kp + 1]);
}

template <int HW>
__global__ void prep_in_f16(const float* __restrict__ in,
                            uint32_t* __restrict__ of) {
    int idx = blockIdx.x * 256 + threadIdx.x;
    if (idx >= 128 * 64 * HW) return;
    int p = idx / (64 * HW);
    int rem = idx - p * (64 * HW);
    int b = rem / HW, pix = rem - b * HW;
    const float* src = in + (size_t)b * 256 * HW + (2 * p) * HW + pix;
    of[idx] = pack2h(src[0], src[HW]);
}

// ---------------------------------------------------------------------------
// Tensor-core GEMM (fp16 x fp16, fp32 accum): C = A*B + BN (+ReLU).
// 1 mma per fragment pair. Error = A-quant + B-quant (~2^-11 RMS each).
// MODE 0: implicit-GEMM 3x3 conv (k = tap*256+ic). MODE 1: 1x1 conv.
// EPI 0: fp32 NCHW. EPI 1: packed fp16 [kpair][n].
// R5-proven schedule: M=128 x N=128 x K=32/stage, RSTR=20, double-buffered,
// late-issue stageA, 2 CTAs/SM.
// ---------------------------------------------------------------------------
template <int MODE, int HIN, int WIN, int KT, bool RELU, int EPI>
__global__ void __launch_bounds__(256, 2)
gemm_f16_kernel(const uint32_t* __restrict__ bF_src,
                const uint32_t* __restrict__ aF_src,
                const float* __restrict__ bn, float* __restrict__ out,
                uint16_t* __restrict__ outF) {
    constexpr int WOUT = WIN - 2;
    constexpr int PXB  = (MODE == 0) ? (HIN - 2) * WOUT : 625;
    constexpr int NP   = 64 * PXB;
    constexpr int HW   = HIN * WIN;
    constexpr int S    = KT / 32;
    constexpr int RSTR = 20;
    constexpr int TILE = 128 * RSTR;
    constexpr int TPB  = 2;                  // A, B per buffer
    constexpr int AR   = (MODE == 0) ? 128 : (KT / 2);
    constexpr int PLSTR = 64 * HW;

    extern __shared__ uint32_t smem[];
    const uint32_t smb = smem_u32(smem);

    const int tid  = threadIdx.x;
    const int warp = tid >> 5;
    const int lane = tid & 31;
    const int gid  = lane >> 2;
    const int tig  = lane & 3;
    const int moff = (warp >> 1) * 32;
    const int noff = (warp & 1) * 64;

    const int oc0 = blockIdx.y * 128;
    const int p0  = blockIdx.x * 128;

    const int aRow = lane & 15;
    const int aCol = (lane >> 4) * 4;
    const int bRow = (lane & 7) + ((lane >> 4) & 1) * 8;
    const int bCol = ((lane >> 3) & 1) * 4;

    const int nloc  = tid & 127;
    const int nglob = p0 + nloc;
    const bool nvalid = (nglob < NP);
    int bbase = 0;
    if (MODE == 0) {
        int nn = nvalid ? nglob : 0;
        int b = nn / PXB; int rem = nn - b * PXB;
        int y = rem / WOUT; int x = rem - y * WOUT;
        bbase = b * HW + y * WIN + x;
    }

    float acc[2][8][4];
#pragma unroll
    for (int a = 0; a < 2; a++)
#pragma unroll
        for (int b = 0; b < 8; b++)
#pragma unroll
            for (int c = 0; c < 4; c++) acc[a][b][c] = 0.f;

    auto prefetchB = [&](int s, uint32_t v[2][4]) {
        int tapoff = 0, plane0 = 0;
        if (MODE == 0) {
            int tap = s >> 3; plane0 = (s & 7) * 16;
            tapoff = (tap / 3) * WIN + (tap % 3);
        }
#pragma unroll
        for (int i = 0; i < 2; i++) {
            int task = tid + 256 * i;
            int wg = (task >> 7) & 3;
#pragma unroll
            for (int j = 0; j < 4; j++) {
                int w = wg * 4 + j;
                long addr = (MODE == 0)
                    ? (long)(plane0 + w) * PLSTR + bbase + tapoff
                    : (long)(s * 16 + w) * 40000 + nglob;
                v[i][j] = nvalid ? __ldg(bF_src + addr) : 0u;
            }
        }
    };
    auto storeB = [&](int buf, uint32_t v[2][4]) {
#pragma unroll
        for (int i = 0; i < 2; i++) {
            int task = tid + 256 * i;
            int wg = (task >> 7) & 3;
            uint32_t* dst = &smem[(buf * TPB + 1) * TILE + nloc * RSTR + wg * 4];
            *reinterpret_cast<uint4*>(dst) =
                make_uint4(v[i][0], v[i][1], v[i][2], v[i][3]);
        }
    };
    auto stageA = [&](int buf, int s) {
        int abase;
        if (MODE == 0) {
            int tap = s >> 3; int plane0 = (s & 7) * 16;
            abase = tap * 32768 + oc0 * 128 + plane0;
        } else {
            abase = oc0 * (KT / 2) + s * 16;
        }
#pragma unroll
        for (int i = 0; i < 2; i++) {
            int task = tid + 256 * i;      // 512 tasks: 128 rows x 4 c-groups
            int r = task >> 2;
            int c = (task & 3) * 4;
            const uint32_t* src = aF_src + abase + r * AR + c;
            uint32_t dst = smb + ((buf * TPB) * TILE + r * RSTR + c) * 4;
            CP_ASYNC16(dst, src);
        }
    };

    // prologue: fill buf 0
    {
        uint32_t v[2][4];
        prefetchB(0, v);
        storeB(0, v);
        stageA(0, 0);
        CP_COMMIT();
    }

    for (int s = 0; s < S; s++) {
        const int buf = s & 1;
        CP_WAIT0();
        __syncthreads();

        const bool have = (s + 1 < S);
        uint32_t vpre[2][4];
        if (have) prefetchB(s + 1, vpre);

        const uint32_t smA = smb + (buf * TPB + 0) * TILE * 4;
        const uint32_t smB = smb + (buf * TPB + 1) * TILE * 4;
#pragma unroll
        for (int kc = 0; kc < 2; kc++) {
            uint32_t af[2][4];
#pragma unroll
            for (int mf = 0; mf < 2; mf++) {
                uint32_t off = ((moff + mf * 16 + aRow) * RSTR + kc * 8 + aCol) * 4;
                ldm4(af[mf], smA + off);
            }
#pragma unroll
            for (int nfp = 0; nfp < 4; nfp++) {
                uint32_t boff = ((noff + nfp * 16 + bRow) * RSTR + kc * 8 + bCol) * 4;
                uint32_t bf[4];
                ldm4(bf, smB + boff);
#pragma unroll
                for (int snf = 0; snf < 2; snf++) {
                    int nf = nfp * 2 + snf;
#pragma unroll
                    for (int mf = 0; mf < 2; mf++)
                        mma_f16(acc[mf][nf], af[mf], &bf[2 * snf]);
                }
            }
        }

        if (have) {
            storeB(buf ^ 1, vpre);
            stageA(buf ^ 1, s + 1);   // late issue (R5-proven order)
            CP_COMMIT();
        }
    }

    // epilogue
    __syncthreads();
    float* Cs = (float*)smem;                // 128 x 132 fp32 (67584 B)
#pragma unroll
    for (int mf = 0; mf < 2; mf++) {
#pragma unroll
        for (int nf = 0; nf < 8; nf++) {
            int m0 = moff + mf * 16 + gid;
            int nl = noff + nf * 8 + 2 * tig;
            *(float2*)&Cs[m0 * 132 + nl]       = make_float2(acc[mf][nf][0], acc[mf][nf][1]);
            *(float2*)&Cs[(m0 + 8) * 132 + nl] = make_float2(acc[mf][nf][2], acc[mf][nf][3]);
        }
    }
    __syncthreads();

    for (int t = warp; t < 128; t += 8) {
        const int oc = oc0 + t;
        const float g  = bn[oc];
        const float be = bn[256 + oc];
        const float mm = bn[512 + oc];
        const float vv = bn[768 + oc];
        const float inv  = g * rsqrtf(vv + EPS_);
        const float bias = be - mm * inv;
#pragma unroll
        for (int cc0 = 0; cc0 < 128; cc0 += 32) {
            int cc = cc0 + lane;
            int n = p0 + cc;
            if (n < NP) {
                float val = Cs[t * 132 + cc] * inv + bias;
                if (RELU) val = fmaxf(val, 0.f);
                if (EPI == 0) {
                    int b = n / PXB; int rq = n - b * PXB;
                    out[((size_t)(b * 256 + oc)) * PXB + rq] = val;
                } else {
                    __half hv = __float2half_rn(val);
                    outF[(size_t)(oc >> 1) * 80000 + n * 2 + (oc & 1)] =
                        *reinterpret_cast<uint16_t*>(&hv);
                }
            }
        }
    }
}

// ---------------------------------------------------------------------------
// Multi-scale depthwise xcorr, paired channels, single fp16 packed output.
// ---------------------------------------------------------------------------
__global__ void multixcorr_kernel(const float* __restrict__ s,
                                  const float* __restrict__ k,
                                  uint32_t* __restrict__ ff) {
    const int kp0 = blockIdx.x;   // 0..127
    const int b   = blockIdx.y;

    __shared__ float ss[2][841];
    __shared__ float kk[2][25];

    const float* sp = s + ((size_t)b * HID_ + 2 * kp0) * 841;
    const float* kp = k + ((size_t)b * HID_ + 2 * kp0) * 25;

    for (int i = threadIdx.x; i < 2 * 841; i += blockDim.x)
        ss[i / 841][i % 841] = sp[i];
    if (threadIdx.x < 50) kk[threadIdx.x / 25][threadIdx.x % 25] = kp[threadIdx.x];
    __syncthreads();

    for (int p = threadIdx.x; p < 625; p += blockDim.x) {
        const int y = p / 25, x = p - (p / 25) * 25;
        float f0[2], f1[2], f2[2];
#pragma unroll
        for (int h = 0; h < 2; h++) {
            float s_full = 0.f, s_in = 0.f;
#pragma unroll
            for (int dy = 0; dy < 5; dy++)
#pragma unroll
                for (int dx = 0; dx < 5; dx++) {
                    float vv = ss[h][(y + dy) * 29 + (x + dx)] * kk[h][dy * 5 + dx];
                    s_full += vv;
                    if (dy >= 1 && dy <= 3 && dx >= 1 && dx <= 3) s_in += vv;
                }
            f0[h] = s_full;
            f1[h] = s_in;
            f2[h] = ss[h][(y + 2) * 29 + (x + 2)] * kk[h][12];
        }
        const int n = b * 625 + p;
        ff[(size_t)kp0 * 40000 + n]         = pack2h(f0[0], f0[1]);
        ff[(size_t)(128 + kp0) * 40000 + n] = pack2h(f1[0], f1[1]);
        ff[(size_t)(256 + kp0) * 40000 + n] = pack2h(f2[0], f2[1]);
    }
}

// ---------------------------------------------------------------------------
// Final 1x1: (B,256,625) x (10,256) + bias -> (B,10,625). grid (B, 5).
// ---------------------------------------------------------------------------
__global__ void conv1x1_out_kernel(const float* __restrict__ in,
                                   const float* __restrict__ w,
                                   const float* __restrict__ bias,
                                   float* __restrict__ out) {
    const int b = blockIdx.x;
    const int chunk = blockIdx.y;

    __shared__ float wsm[COUT_ * HID_];
    for (int i = threadIdx.x; i < COUT_ * HID_; i += blockDim.x) wsm[i] = w[i];
    __syncthreads();

    const float* ib = in + (size_t)b * HID_ * 625;
    float* ob = out + (size_t)b * COUT_ * 625;

    const int pend = min(625, (chunk + 1) * 125);
    for (int p = chunk * 125 + threadIdx.x; p < pend; p += blockDim.x) {
        float acc[COUT_];
#pragma unroll
        for (int o = 0; o < COUT_; o++) acc[o] = bias[o];
        for (int c = 0; c < HID_; c++) {
            float vv = ib[(size_t)c * 625 + p];
#pragma unroll
            for (int o = 0; o < COUT_; o++) acc[o] = fmaf(vv, wsm[o * HID_ + c], acc[o]);
        }
#pragma unroll
        for (int o = 0; o < COUT_; o++) ob[(size_t)o * 625 + p] = acc[o];
    }
}

// ---------------------------------------------------------------------------
extern "C" void kernel_launch(void* const* d_in, const int* in_sizes, int n_in,
                              void* d_out, int out_size) {
    const float* kernel_in = (const float*)d_in[0];
    const float* search_in = (const float*)d_in[1];
    const float* wk  = (const float*)d_in[2];
    const float* bnk = (const float*)d_in[3];
    const float* ws  = (const float*)d_in[4];
    const float* bns = (const float*)d_in[5];
    const float* wd  = (const float*)d_in[6];
    const float* bnd = (const float*)d_in[7];
    const float* wh1 = (const float*)d_in[8];
    const float* bnh = (const float*)d_in[9];
    const float* wh2 = (const float*)d_in[10];
    const float* bh2 = (const float*)d_in[11];
    float* out = (float*)d_out;

    float *kfeat, *sfeat, *h;
    uint32_t *wkF, *wsF, *wdF, *wh1F;
    uint32_t *kinF, *sinF, *featF, *f2F;
    cudaGetSymbolAddress((void**)&kfeat, g_kfeat);
    cudaGetSymbolAddress((void**)&sfeat, g_sfeat);
    cudaGetSymbolAddress((void**)&h,     g_h);
    cudaGetSymbolAddress((void**)&wkF, g_wk);
    cudaGetSymbolAddress((void**)&wsF, g_ws);
    cudaGetSymbolAddress((void**)&wdF, g_wd);
    cudaGetSymbolAddress((void**)&wh1F, g_wh1);
    cudaGetSymbolAddress((void**)&kinF, g_kinF);
    cudaGetSymbolAddress((void**)&sinF, g_sinF);
    cudaGetSymbolAddress((void**)&featF, g_featF);
    cudaGetSymbolAddress((void**)&f2F, g_f2F);

    constexpr int SMEM = 128 * 132 * 4;   // 67584 (staging 2x2 tiles = 40960 < epi)

    cudaFuncSetAttribute(gemm_f16_kernel<0, 7, 7, 2304, true, 0>,
                         cudaFuncAttributeMaxDynamicSharedMemorySize, SMEM);
    cudaFuncSetAttribute(gemm_f16_kernel<0, 31, 31, 2304, true, 0>,
                         cudaFuncAttributeMaxDynamicSharedMemorySize, SMEM);
    cudaFuncSetAttribute(gemm_f16_kernel<1, 3, 3, 768, false, 1>,
                         cudaFuncAttributeMaxDynamicSharedMemorySize, SMEM);
    cudaFuncSetAttribute(gemm_f16_kernel<1, 3, 3, 256, true, 0>,
                         cudaFuncAttributeMaxDynamicSharedMemorySize, SMEM);

    // #0-#2: dependencies of gemm_s (ncu window = launch index 3)
    prep_in_f16<961><<<(128 * 64 * 961 + 255) / 256, 256>>>(search_in, sinF);   // 0
    prep_w3_f16<<<(9 * 256 * 128 + 255) / 256, 256>>>(ws, wsF);                 // 1
    prep_w1_f16<768><<<(256 * 384 + 255) / 256, 256>>>(wd, wdF);                // 2

    // #3: search branch conv3x3 -> g_sfeat  [PROFILED]
    gemm_f16_kernel<0, 31, 31, 2304, true, 0><<<dim3(421, 2), 256, SMEM>>>(
        sinF, wsF, bns, sfeat, nullptr);

    // remaining preps
    prep_w3_f16<<<(9 * 256 * 128 + 255) / 256, 256>>>(wk, wkF);                 // 4
    prep_w1_f16<256><<<(256 * 128 + 255) / 256, 256>>>(wh1, wh1F);              // 5
    prep_in_f16<49><<<(128 * 64 * 49 + 255) / 256, 256>>>(kernel_in, kinF);     // 6

    // kernel branch conv3x3 -> g_kfeat
    gemm_f16_kernel<0, 7, 7, 2304, true, 0><<<dim3(13, 2), 256, SMEM>>>(
        kinF, wkF, bnk, kfeat, nullptr);
    // xcorr -> packed featF (single fp16)
    multixcorr_kernel<<<dim3(128, B_), 256>>>(sfeat, kfeat, featF);
    // wd + bn -> packed f2F
    gemm_f16_kernel<1, 3, 3, 768, false, 1><<<dim3(313, 2), 256, SMEM>>>(
        featF, wdF, bnd, nullptr, (uint16_t*)f2F);
    // wh1 + bn + relu -> g_h
    gemm_f16_kernel<1, 3, 3, 256, true, 0><<<dim3(313, 2), 256, SMEM>>>(
        f2F, wh1F, bnh, h, nullptr);
    // wh2 + bias -> out
    conv1x1_out_kernel<<<dim3(B_, 5), 128>>>(h, wh2, bh2, out);
}

// round 14
// speedup vs baseline: 2.1412x; 1.0427x over previous
#include <cuda_runtime.h>
#include <cuda_fp16.h>
#include <math.h>
#include <stdint.h>

#define B_    64
#define CIN_  256
#define HID_  256
#define COUT_ 10
#define EPS_  1e-5f

// ---------------------------------------------------------------------------
// Device globals (no runtime allocation allowed)
// ---------------------------------------------------------------------------
__device__ float g_kfeat[B_ * HID_ * 25];        // (64,256,5,5)
__device__ float g_sfeat[B_ * HID_ * 841];       // (64,256,29,29)
__device__ float g_h    [B_ * HID_ * 625];       // (64,256,25,25)
// fp16 packed (single) weights, smem-ready order
__device__ __align__(16) uint32_t g_wk[9 * 256 * 128];
__device__ __align__(16) uint32_t g_ws[9 * 256 * 128];
__device__ __align__(16) uint32_t g_wd[256 * 384];
__device__ __align__(16) uint32_t g_wh1[256 * 128];
// fp16 packed (single) inputs: [icpair 128][b 64][HW]
__device__ __align__(16) uint32_t g_kinF[128 * 64 * 49];
__device__ __align__(16) uint32_t g_sinF[128 * 64 * 961];
// fp16 packed (single) activations: [kpair][n=40000]
__device__ __align__(16) uint32_t g_featF[384 * 40000];
__device__ __align__(16) uint32_t g_f2F [128 * 40000];

// ---------------------------------------------------------------------------
// PTX helpers (baseline ISA only; compiles for plain compute_103)
// ---------------------------------------------------------------------------
__device__ __forceinline__ void mma_f16(float* c, const uint32_t* a,
                                        const uint32_t* b) {
    asm volatile(
        "mma.sync.aligned.m16n8k16.row.col.f32.f16.f16.f32 "
        "{%0,%1,%2,%3}, {%4,%5,%6,%7}, {%8,%9}, {%0,%1,%2,%3};"
        : "+f"(c[0]), "+f"(c[1]), "+f"(c[2]), "+f"(c[3])
        : "r"(a[0]), "r"(a[1]), "r"(a[2]), "r"(a[3]), "r"(b[0]), "r"(b[1]));
}

__device__ __forceinline__ void ldm4(uint32_t* d, uint32_t addr) {
    asm volatile("ldmatrix.sync.aligned.m8n8.x4.shared.b16 {%0,%1,%2,%3}, [%4];"
                 : "=r"(d[0]), "=r"(d[1]), "=r"(d[2]), "=r"(d[3]) : "r"(addr));
}

__device__ __forceinline__ uint32_t smem_u32(const void* p) {
    uint32_t a;
    asm("{ .reg .u64 t; cvta.to.shared.u64 t, %1; cvt.u32.u64 %0, t; }"
        : "=r"(a) : "l"(p));
    return a;
}

#define CP_ASYNC16(dst, src) \
    asm volatile("cp.async.cg.shared.global [%0], [%1], 16;" :: "r"(dst), "l"(src))
#define CP_COMMIT()  asm volatile("cp.async.commit_group;")
#define CP_WAIT0()   asm volatile("cp.async.wait_group 0;" ::: "memory")

__device__ __forceinline__ uint32_t pack2h(float a, float b) {
    __half2 H = __floats2half2_rn(a, b);
    return *reinterpret_cast<uint32_t*>(&H);
}

// ---------------------------------------------------------------------------
// Prep kernels (single fp16)
// ---------------------------------------------------------------------------
__global__ void prep_w3_f16(const float* __restrict__ w,
                            uint32_t* __restrict__ of) {
    int idx = blockIdx.x * 256 + threadIdx.x;
    if (idx >= 9 * 256 * 128) return;
    int tap = idx >> 15;
    int rem = idx & 32767;
    int oc = rem >> 7, p = rem & 127;
    of[idx] = pack2h(w[(size_t)oc * 2304 + (2 * p) * 9 + tap],
                     w[(size_t)oc * 2304 + (2 * p + 1) * 9 + tap]);
}

template <int K>
__global__ void prep_w1_f16(const float* __restrict__ w,
                            uint32_t* __restrict__ of) {
    int idx = blockIdx.x * 256 + threadIdx.x;
    if (idx >= 256 * (K / 2)) return;
    int oc = idx / (K / 2), kp = idx - oc * (K / 2);
    of[idx] = pack2h(w[(size_t)oc * K + 2 * kp], w[(size_t)oc * K + 2 * kp + 1]);
}

template <int HW>
__global__ void prep_in_f16(const float* __restrict__ in,
                            uint32_t* __restrict__ of) {
    int idx = blockIdx.x * 256 + threadIdx.x;
    if (idx >= 128 * 64 * HW) return;
    int p = idx / (64 * HW);
    int rem = idx - p * (64 * HW);
    int b = rem / HW, pix = rem - b * HW;
    const float* src = in + (size_t)b * 256 * HW + (2 * p) * HW + pix;
    of[idx] = pack2h(src[0], src[HW]);
}

// ---------------------------------------------------------------------------
// Tensor-core GEMM (fp16 x fp16, fp32 accum): C = A*B + BN (+ReLU).
// MODE 0: implicit-GEMM 3x3 conv (k = tap*256+ic). MODE 1: 1x1 conv.
// EPI 0: fp32 NCHW. EPI 1: packed fp16 [kpair][n].
// Schedule: M=128 x N=128 x K=32/stage, RSTR=20, double-buffered, 2 CTAs/SM.
// stageA cp.async issued AFTER prefetchB LDGs but BEFORE the mma burst:
// B loads keep LSU priority; A's latency hides behind ~1200 cyc of mma.
// ---------------------------------------------------------------------------
template <int MODE, int HIN, int WIN, int KT, bool RELU, int EPI>
__global__ void __launch_bounds__(256, 2)
gemm_f16_kernel(const uint32_t* __restrict__ bF_src,
                const uint32_t* __restrict__ aF_src,
                const float* __restrict__ bn, float* __restrict__ out,
                uint16_t* __restrict__ outF) {
    constexpr int WOUT = WIN - 2;
    constexpr int PXB  = (MODE == 0) ? (HIN - 2) * WOUT : 625;
    constexpr int NP   = 64 * PXB;
    constexpr int HW   = HIN * WIN;
    constexpr int S    = KT / 32;
    constexpr int RSTR = 20;
    constexpr int TILE = 128 * RSTR;
    constexpr int TPB  = 2;                  // A, B per buffer
    constexpr int AR   = (MODE == 0) ? 128 : (KT / 2);
    constexpr int PLSTR = 64 * HW;

    extern __shared__ uint32_t smem[];
    const uint32_t smb = smem_u32(smem);

    const int tid  = threadIdx.x;
    const int warp = tid >> 5;
    const int lane = tid & 31;
    const int gid  = lane >> 2;
    const int tig  = lane & 3;
    const int moff = (warp >> 1) * 32;
    const int noff = (warp & 1) * 64;

    const int oc0 = blockIdx.y * 128;
    const int p0  = blockIdx.x * 128;

    const int aRow = lane & 15;
    const int aCol = (lane >> 4) * 4;
    const int bRow = (lane & 7) + ((lane >> 4) & 1) * 8;
    const int bCol = ((lane >> 3) & 1) * 4;

    const int nloc  = tid & 127;
    const int nglob = p0 + nloc;
    const bool nvalid = (nglob < NP);
    int bbase = 0;
    if (MODE == 0) {
        int nn = nvalid ? nglob : 0;
        int b = nn / PXB; int rem = nn - b * PXB;
        int y = rem / WOUT; int x = rem - y * WOUT;
        bbase = b * HW + y * WIN + x;
    }

    float acc[2][8][4];
#pragma unroll
    for (int a = 0; a < 2; a++)
#pragma unroll
        for (int b = 0; b < 8; b++)
#pragma unroll
            for (int c = 0; c < 4; c++) acc[a][b][c] = 0.f;

    auto prefetchB = [&](int s, uint32_t v[2][4]) {
        int tapoff = 0, plane0 = 0;
        if (MODE == 0) {
            int tap = s >> 3; plane0 = (s & 7) * 16;
            tapoff = (tap / 3) * WIN + (tap % 3);
        }
#pragma unroll
        for (int i = 0; i < 2; i++) {
            int task = tid + 256 * i;
            int wg = (task >> 7) & 3;
#pragma unroll
            for (int j = 0; j < 4; j++) {
                int w = wg * 4 + j;
                long addr = (MODE == 0)
                    ? (long)(plane0 + w) * PLSTR + bbase + tapoff
                    : (long)(s * 16 + w) * 40000 + nglob;
                v[i][j] = nvalid ? __ldg(bF_src + addr) : 0u;
            }
        }
    };
    auto storeB = [&](int buf, uint32_t v[2][4]) {
#pragma unroll
        for (int i = 0; i < 2; i++) {
            int task = tid + 256 * i;
            int wg = (task >> 7) & 3;
            uint32_t* dst = &smem[(buf * TPB + 1) * TILE + nloc * RSTR + wg * 4];
            *reinterpret_cast<uint4*>(dst) =
                make_uint4(v[i][0], v[i][1], v[i][2], v[i][3]);
        }
    };
    auto stageA = [&](int buf, int s) {
        int abase;
        if (MODE == 0) {
            int tap = s >> 3; int plane0 = (s & 7) * 16;
            abase = tap * 32768 + oc0 * 128 + plane0;
        } else {
            abase = oc0 * (KT / 2) + s * 16;
        }
#pragma unroll
        for (int i = 0; i < 2; i++) {
            int task = tid + 256 * i;      // 512 tasks: 128 rows x 4 c-groups
            int r = task >> 2;
            int c = (task & 3) * 4;
            const uint32_t* src = aF_src + abase + r * AR + c;
            uint32_t dst = smb + ((buf * TPB) * TILE + r * RSTR + c) * 4;
            CP_ASYNC16(dst, src);
        }
    };

    // prologue: fill buf 0
    {
        uint32_t v[2][4];
        prefetchB(0, v);
        storeB(0, v);
        stageA(0, 0);
        CP_COMMIT();
    }

    for (int s = 0; s < S; s++) {
        const int buf = s & 1;
        CP_WAIT0();
        __syncthreads();

        const bool have = (s + 1 < S);
        uint32_t vpre[2][4];
        if (have) {
            prefetchB(s + 1, vpre);      // B LDGs first (late-consumed operand)
            stageA(buf ^ 1, s + 1);      // then A cp.async: hides behind mma
            CP_COMMIT();
        }

        const uint32_t smA = smb + (buf * TPB + 0) * TILE * 4;
        const uint32_t smB = smb + (buf * TPB + 1) * TILE * 4;
#pragma unroll
        for (int kc = 0; kc < 2; kc++) {
            uint32_t af[2][4];
#pragma unroll
            for (int mf = 0; mf < 2; mf++) {
                uint32_t off = ((moff + mf * 16 + aRow) * RSTR + kc * 8 + aCol) * 4;
                ldm4(af[mf], smA + off);
            }
#pragma unroll
            for (int nfp = 0; nfp < 4; nfp++) {
                uint32_t boff = ((noff + nfp * 16 + bRow) * RSTR + kc * 8 + bCol) * 4;
                uint32_t bf[4];
                ldm4(bf, smB + boff);
#pragma unroll
                for (int snf = 0; snf < 2; snf++) {
                    int nf = nfp * 2 + snf;
#pragma unroll
                    for (int mf = 0; mf < 2; mf++)
                        mma_f16(acc[mf][nf], af[mf], &bf[2 * snf]);
                }
            }
        }

        if (have) storeB(buf ^ 1, vpre);
    }

    // epilogue
    __syncthreads();
    float* Cs = (float*)smem;                // 128 x 132 fp32 (67584 B)
#pragma unroll
    for (int mf = 0; mf < 2; mf++) {
#pragma unroll
        for (int nf = 0; nf < 8; nf++) {
            int m0 = moff + mf * 16 + gid;
            int nl = noff + nf * 8 + 2 * tig;
            *(float2*)&Cs[m0 * 132 + nl]       = make_float2(acc[mf][nf][0], acc[mf][nf][1]);
            *(float2*)&Cs[(m0 + 8) * 132 + nl] = make_float2(acc[mf][nf][2], acc[mf][nf][3]);
        }
    }
    __syncthreads();

    for (int t = warp; t < 128; t += 8) {
        const int oc = oc0 + t;
        const float g  = bn[oc];
        const float be = bn[256 + oc];
        const float mm = bn[512 + oc];
        const float vv = bn[768 + oc];
        const float inv  = g * rsqrtf(vv + EPS_);
        const float bias = be - mm * inv;
#pragma unroll
        for (int cc0 = 0; cc0 < 128; cc0 += 32) {
            int cc = cc0 + lane;
            int n = p0 + cc;
            if (n < NP) {
                float val = Cs[t * 132 + cc] * inv + bias;
                if (RELU) val = fmaxf(val, 0.f);
                if (EPI == 0) {
                    int b = n / PXB; int rq = n - b * PXB;
                    out[((size_t)(b * 256 + oc)) * PXB + rq] = val;
                } else {
                    __half hv = __float2half_rn(val);
                    outF[(size_t)(oc >> 1) * 80000 + n * 2 + (oc & 1)] =
                        *reinterpret_cast<uint16_t*>(&hv);
                }
            }
        }
    }
}

// ---------------------------------------------------------------------------
// Multi-scale depthwise xcorr, paired channels, single fp16 packed output.
// ---------------------------------------------------------------------------
__global__ void multixcorr_kernel(const float* __restrict__ s,
                                  const float* __restrict__ k,
                                  uint32_t* __restrict__ ff) {
    const int kp0 = blockIdx.x;   // 0..127
    const int b   = blockIdx.y;

    __shared__ float ss[2][841];
    __shared__ float kk[2][25];

    const float* sp = s + ((size_t)b * HID_ + 2 * kp0) * 841;
    const float* kp = k + ((size_t)b * HID_ + 2 * kp0) * 25;

    for (int i = threadIdx.x; i < 2 * 841; i += blockDim.x)
        ss[i / 841][i % 841] = sp[i];
    if (threadIdx.x < 50) kk[threadIdx.x / 25][threadIdx.x % 25] = kp[threadIdx.x];
    __syncthreads();

    for (int p = threadIdx.x; p < 625; p += blockDim.x) {
        const int y = p / 25, x = p - (p / 25) * 25;
        float f0[2], f1[2], f2[2];
#pragma unroll
        for (int h = 0; h < 2; h++) {
            float s_full = 0.f, s_in = 0.f;
#pragma unroll
            for (int dy = 0; dy < 5; dy++)
#pragma unroll
                for (int dx = 0; dx < 5; dx++) {
                    float vv = ss[h][(y + dy) * 29 + (x + dx)] * kk[h][dy * 5 + dx];
                    s_full += vv;
                    if (dy >= 1 && dy <= 3 && dx >= 1 && dx <= 3) s_in += vv;
                }
            f0[h] = s_full;
            f1[h] = s_in;
            f2[h] = ss[h][(y + 2) * 29 + (x + 2)] * kk[h][12];
        }
        const int n = b * 625 + p;
        ff[(size_t)kp0 * 40000 + n]         = pack2h(f0[0], f0[1]);
        ff[(size_t)(128 + kp0) * 40000 + n] = pack2h(f1[0], f1[1]);
        ff[(size_t)(256 + kp0) * 40000 + n] = pack2h(f2[0], f2[1]);
    }
}

// ---------------------------------------------------------------------------
// Final 1x1: (B,256,625) x (10,256) + bias -> (B,10,625). grid (B, 5).
// ---------------------------------------------------------------------------
__global__ void conv1x1_out_kernel(const float* __restrict__ in,
                                   const float* __restrict__ w,
                                   const float* __restrict__ bias,
                                   float* __restrict__ out) {
    const int b = blockIdx.x;
    const int chunk = blockIdx.y;

    __shared__ float wsm[COUT_ * HID_];
    for (int i = threadIdx.x; i < COUT_ * HID_; i += blockDim.x) wsm[i] = w[i];
    __syncthreads();

    const float* ib = in + (size_t)b * HID_ * 625;
    float* ob = out + (size_t)b * COUT_ * 625;

    const int pend = min(625, (chunk + 1) * 125);
    for (int p = chunk * 125 + threadIdx.x; p < pend; p += blockDim.x) {
        float acc[COUT_];
#pragma unroll
        for (int o = 0; o < COUT_; o++) acc[o] = bias[o];
        for (int c = 0; c < HID_; c++) {
            float vv = ib[(size_t)c * 625 + p];
#pragma unroll
            for (int o = 0; o < COUT_; o++) acc[o] = fmaf(vv, wsm[o * HID_ + c], acc[o]);
        }
#pragma unroll
        for (int o = 0; o < COUT_; o++) ob[(size_t)o * 625 + p] = acc[o];
    }
}

// ---------------------------------------------------------------------------
extern "C" void kernel_launch(void* const* d_in, const int* in_sizes, int n_in,
                              void* d_out, int out_size) {
    const float* kernel_in = (const float*)d_in[0];
    const float* search_in = (const float*)d_in[1];
    const float* wk  = (const float*)d_in[2];
    const float* bnk = (const float*)d_in[3];
    const float* ws  = (const float*)d_in[4];
    const float* bns = (const float*)d_in[5];
    const float* wd  = (const float*)d_in[6];
    const float* bnd = (const float*)d_in[7];
    const float* wh1 = (const float*)d_in[8];
    const float* bnh = (const float*)d_in[9];
    const float* wh2 = (const float*)d_in[10];
    const float* bh2 = (const float*)d_in[11];
    float* out = (float*)d_out;

    float *kfeat, *sfeat, *h;
    uint32_t *wkF, *wsF, *wdF, *wh1F;
    uint32_t *kinF, *sinF, *featF, *f2F;
    cudaGetSymbolAddress((void**)&kfeat, g_kfeat);
    cudaGetSymbolAddress((void**)&sfeat, g_sfeat);
    cudaGetSymbolAddress((void**)&h,     g_h);
    cudaGetSymbolAddress((void**)&wkF, g_wk);
    cudaGetSymbolAddress((void**)&wsF, g_ws);
    cudaGetSymbolAddress((void**)&wdF, g_wd);
    cudaGetSymbolAddress((void**)&wh1F, g_wh1);
    cudaGetSymbolAddress((void**)&kinF, g_kinF);
    cudaGetSymbolAddress((void**)&sinF, g_sinF);
    cudaGetSymbolAddress((void**)&featF, g_featF);
    cudaGetSymbolAddress((void**)&f2F, g_f2F);

    constexpr int SMEM = 128 * 132 * 4;   // 67584 (staging 2x2 tiles = 40960 < epi)

    cudaFuncSetAttribute(gemm_f16_kernel<0, 7, 7, 2304, true, 0>,
                         cudaFuncAttributeMaxDynamicSharedMemorySize, SMEM);
    cudaFuncSetAttribute(gemm_f16_kernel<0, 31, 31, 2304, true, 0>,
                         cudaFuncAttributeMaxDynamicSharedMemorySize, SMEM);
    cudaFuncSetAttribute(gemm_f16_kernel<1, 3, 3, 768, false, 1>,
                         cudaFuncAttributeMaxDynamicSharedMemorySize, SMEM);
    cudaFuncSetAttribute(gemm_f16_kernel<1, 3, 3, 256, true, 0>,
                         cudaFuncAttributeMaxDynamicSharedMemorySize, SMEM);

    // #0-#2: dependencies of gemm_s (ncu window = launch index 3)
    prep_in_f16<961><<<(128 * 64 * 961 + 255) / 256, 256>>>(search_in, sinF);   // 0
    prep_w3_f16<<<(9 * 256 * 128 + 255) / 256, 256>>>(ws, wsF);                 // 1
    prep_w1_f16<768><<<(256 * 384 + 255) / 256, 256>>>(wd, wdF);                // 2

    // #3: search branch conv3x3 -> g_sfeat  [PROFILED]
    gemm_f16_kernel<0, 31, 31, 2304, true, 0><<<dim3(421, 2), 256, SMEM>>>(
        sinF, wsF, bns, sfeat, nullptr);

    // remaining preps
    prep_w3_f16<<<(9 * 256 * 128 + 255) / 256, 256>>>(wk, wkF);                 // 4
    prep_w1_f16<256><<<(256 * 128 + 255) / 256, 256>>>(wh1, wh1F);              // 5
    prep_in_f16<49><<<(128 * 64 * 49 + 255) / 256, 256>>>(kernel_in, kinF);     // 6

    // kernel branch conv3x3 -> g_kfeat
    gemm_f16_kernel<0, 7, 7, 2304, true, 0><<<dim3(13, 2), 256, SMEM>>>(
        kinF, wkF, bnk, kfeat, nullptr);
    // xcorr -> packed featF (single fp16)
    multixcorr_kernel<<<dim3(128, B_), 256>>>(sfeat, kfeat, featF);
    // wd + bn -> packed f2F
    gemm_f16_kernel<1, 3, 3, 768, false, 1><<<dim3(313, 2), 256, SMEM>>>(
        featF, wdF, bnd, nullptr, (uint16_t*)f2F);
    // wh1 + bn + relu -> g_h
    gemm_f16_kernel<1, 3, 3, 256, true, 0><<<dim3(313, 2), 256, SMEM>>>(
        f2F, wh1F, bnh, h, nullptr);
    // wh2 + bias -> out
    conv1x1_out_kernel<<<dim3(B_, 5), 128>>>(h, wh2, bh2, out);
}

// round 15
// speedup vs baseline: 2.1734x; 1.0151x over previous
#include <cuda_runtime.h>
#include <cuda_fp16.h>
#include <math.h>
#include <stdint.h>

#define B_    64
#define CIN_  256
#define HID_  256
#define COUT_ 10
#define EPS_  1e-5f

// ---------------------------------------------------------------------------
// Device globals (no runtime allocation allowed)
// ---------------------------------------------------------------------------
__device__ float g_kfeat[B_ * HID_ * 25];        // (64,256,5,5)
__device__ float g_sfeat[B_ * HID_ * 841];       // (64,256,29,29)
__device__ float g_h    [B_ * HID_ * 625];       // (64,256,25,25)
// fp16 weights pre-packed in m16n8k16 A-fragment order:
//   uint4[ (m16b * (K/16) + kchunk) * 32 + lane ]
__device__ __align__(16) uint4 g_wkA[16 * 144 * 32];
__device__ __align__(16) uint4 g_wsA[16 * 144 * 32];
__device__ __align__(16) uint4 g_wdA[16 * 48 * 32];
__device__ __align__(16) uint4 g_wh1A[16 * 16 * 32];
// fp16 packed (single) inputs: [icpair 128][b 64][HW]
__device__ __align__(16) uint32_t g_kinF[128 * 64 * 49];
__device__ __align__(16) uint32_t g_sinF[128 * 64 * 961];
// fp16 packed (single) activations: [kpair][n=40000]
__device__ __align__(16) uint32_t g_featF[384 * 40000];
__device__ __align__(16) uint32_t g_f2F [128 * 40000];

// ---------------------------------------------------------------------------
// PTX helpers (baseline ISA only; compiles for plain compute_103)
// ---------------------------------------------------------------------------
__device__ __forceinline__ void mma_f16(float* c, const uint32_t* a,
                                        const uint32_t* b) {
    asm volatile(
        "mma.sync.aligned.m16n8k16.row.col.f32.f16.f16.f32 "
        "{%0,%1,%2,%3}, {%4,%5,%6,%7}, {%8,%9}, {%0,%1,%2,%3};"
        : "+f"(c[0]), "+f"(c[1]), "+f"(c[2]), "+f"(c[3])
        : "r"(a[0]), "r"(a[1]), "r"(a[2]), "r"(a[3]), "r"(b[0]), "r"(b[1]));
}

__device__ __forceinline__ void ldm4(uint32_t* d, uint32_t addr) {
    asm volatile("ldmatrix.sync.aligned.m8n8.x4.shared.b16 {%0,%1,%2,%3}, [%4];"
                 : "=r"(d[0]), "=r"(d[1]), "=r"(d[2]), "=r"(d[3]) : "r"(addr));
}

__device__ __forceinline__ uint32_t smem_u32(const void* p) {
    uint32_t a;
    asm("{ .reg .u64 t; cvta.to.shared.u64 t, %1; cvt.u32.u64 %0, t; }"
        : "=r"(a) : "l"(p));
    return a;
}

__device__ __forceinline__ uint32_t pack2h(float a, float b) {
    __half2 H = __floats2half2_rn(a, b);
    return *reinterpret_cast<uint32_t*>(&H);
}

// ---------------------------------------------------------------------------
// Prep kernels
// ---------------------------------------------------------------------------
// w(oc,ic,3,3) -> A-fragment order, k = tap*256 + ic, K = 2304 (144 chunks)
__global__ void prep_w3_frag(const float* __restrict__ w,
                             uint4* __restrict__ of) {
    int idx = blockIdx.x * 256 + threadIdx.x;
    if (idx >= 16 * 144 * 32) return;
    int lane = idx & 31;
    int kc   = (idx >> 5) % 144;
    int m16b = (idx >> 5) / 144;
    int gid = lane >> 2, tig = lane & 3;
    uint32_t r[4];
#pragma unroll
    for (int rr = 0; rr < 4; rr++) {
        int row = m16b * 16 + gid + 8 * (rr & 1);
        int kp  = tig + 4 * (rr >> 1);
        int k0  = kc * 16 + kp * 2;
        int tap0 = k0 >> 8, ic0 = k0 & 255;
        int tap1 = (k0 + 1) >> 8, ic1 = (k0 + 1) & 255;
        r[rr] = pack2h(w[(size_t)row * 2304 + ic0 * 9 + tap0],
                       w[(size_t)row * 2304 + ic1 * 9 + tap1]);
    }
    of[idx] = make_uint4(r[0], r[1], r[2], r[3]);
}

// w(oc,K) -> A-fragment order, k = channel
template <int K>
__global__ void prep_w1_frag(const float* __restrict__ w,
                             uint4* __restrict__ of) {
    int idx = blockIdx.x * 256 + threadIdx.x;
    if (idx >= 16 * (K / 16) * 32) return;
    int lane = idx & 31;
    int kc   = (idx >> 5) % (K / 16);
    int m16b = (idx >> 5) / (K / 16);
    int gid = lane >> 2, tig = lane & 3;
    uint32_t r[4];
#pragma unroll
    for (int rr = 0; rr < 4; rr++) {
        int row = m16b * 16 + gid + 8 * (rr & 1);
        int k0  = kc * 16 + (tig + 4 * (rr >> 1)) * 2;
        r[rr] = pack2h(w[(size_t)row * K + k0], w[(size_t)row * K + k0 + 1]);
    }
    of[idx] = make_uint4(r[0], r[1], r[2], r[3]);
}

template <int HW>
__global__ void prep_in_f16(const float* __restrict__ in,
                            uint32_t* __restrict__ of) {
    int idx = blockIdx.x * 256 + threadIdx.x;
    if (idx >= 128 * 64 * HW) return;
    int p = idx / (64 * HW);
    int rem = idx - p * (64 * HW);
    int b = rem / HW, pix = rem - b * HW;
    const float* src = in + (size_t)b * 256 * HW + (2 * p) * HW + pix;
    of[idx] = pack2h(src[0], src[HW]);
}

// ---------------------------------------------------------------------------
// Tensor-core GEMM (fp16 x fp16, fp32 accum): C = A*B + BN (+ReLU).
// A delivered straight to mma fragment registers via coalesced LDG.128 from
// the pre-packed fragment layout (no A smem tile, no cp.async). B staged via
// LDG->reg->STS double buffer as before. Per-stage smem traffic -37%.
// MODE 0: implicit-GEMM 3x3 conv. MODE 1: 1x1 conv.
// EPI 0: fp32 NCHW. EPI 1: packed fp16 [kpair][n].
// ---------------------------------------------------------------------------
template <int MODE, int HIN, int WIN, int KT, bool RELU, int EPI>
__global__ void __launch_bounds__(256, 2)
gemm_f16_kernel(const uint32_t* __restrict__ bF_src,
                const uint4* __restrict__ aFrag,
                const float* __restrict__ bn, float* __restrict__ out,
                uint16_t* __restrict__ outF) {
    constexpr int WOUT = WIN - 2;
    constexpr int PXB  = (MODE == 0) ? (HIN - 2) * WOUT : 625;
    constexpr int NP   = 64 * PXB;
    constexpr int HW   = HIN * WIN;
    constexpr int S    = KT / 32;
    constexpr int KC16 = KT / 16;
    constexpr int RSTR = 20;
    constexpr int TILE = 128 * RSTR;
    constexpr int PLSTR = 64 * HW;

    extern __shared__ uint32_t smem[];
    const uint32_t smb = smem_u32(smem);

    const int tid  = threadIdx.x;
    const int warp = tid >> 5;
    const int lane = tid & 31;
    const int gid  = lane >> 2;
    const int tig  = lane & 3;
    const int wm   = warp >> 1;
    const int moff = wm * 32;
    const int noff = (warp & 1) * 64;

    const int oc0 = blockIdx.y * 128;
    const int p0  = blockIdx.x * 128;

    const int bRow = (lane & 7) + ((lane >> 4) & 1) * 8;
    const int bCol = ((lane >> 3) & 1) * 4;

    const int nloc  = tid & 127;
    const int nglob = p0 + nloc;
    const bool nvalid = (nglob < NP);
    int bbase = 0;
    if (MODE == 0) {
        int nn = nvalid ? nglob : 0;
        int b = nn / PXB; int rem = nn - b * PXB;
        int y = rem / WOUT; int x = rem - y * WOUT;
        bbase = b * HW + y * WIN + x;
    }

    float acc[2][8][4];
#pragma unroll
    for (int a = 0; a < 2; a++)
#pragma unroll
        for (int b = 0; b < 8; b++)
#pragma unroll
            for (int c = 0; c < 4; c++) acc[a][b][c] = 0.f;

    auto prefetchB = [&](int s, uint32_t v[2][4]) {
        int tapoff = 0, plane0 = 0;
        if (MODE == 0) {
            int tap = s >> 3; plane0 = (s & 7) * 16;
            tapoff = (tap / 3) * WIN + (tap % 3);
        }
#pragma unroll
        for (int i = 0; i < 2; i++) {
            int task = tid + 256 * i;
            int wg = (task >> 7) & 3;
#pragma unroll
            for (int j = 0; j < 4; j++) {
                int w = wg * 4 + j;
                long addr = (MODE == 0)
                    ? (long)(plane0 + w) * PLSTR + bbase + tapoff
                    : (long)(s * 16 + w) * 40000 + nglob;
                v[i][j] = nvalid ? __ldg(bF_src + addr) : 0u;
            }
        }
    };
    auto storeB = [&](int buf, uint32_t v[2][4]) {
#pragma unroll
        for (int i = 0; i < 2; i++) {
            int task = tid + 256 * i;
            int wg = (task >> 7) & 3;
            uint32_t* dst = &smem[buf * TILE + nloc * RSTR + wg * 4];
            *reinterpret_cast<uint4*>(dst) =
                make_uint4(v[i][0], v[i][1], v[i][2], v[i][3]);
        }
    };
    // A fragments for one stage: 4 coalesced LDG.128 per thread
    auto loadA = [&](uint4 af4[2][2], int s) {
#pragma unroll
        for (int kc = 0; kc < 2; kc++)
#pragma unroll
            for (int mf = 0; mf < 2; mf++) {
                size_t idx = ((size_t)(oc0 / 16 + wm * 2 + mf) * KC16
                              + (s * 2 + kc)) * 32 + lane;
                af4[kc][mf] = __ldg(aFrag + idx);
            }
    };

    // prologue: fill buf 0 + A fragments for stage 0
    uint4 af4[2][2];
    {
        uint32_t v[2][4];
        prefetchB(0, v);
        storeB(0, v);
        loadA(af4, 0);
    }

    for (int s = 0; s < S; s++) {
        const int buf = s & 1;
        __syncthreads();

        const bool have = (s + 1 < S);
        uint32_t vpre[2][4];
        if (have) prefetchB(s + 1, vpre);

        const uint32_t smB = smb + buf * TILE * 4;
#pragma unroll
        for (int kc = 0; kc < 2; kc++) {
#pragma unroll
            for (int nfp = 0; nfp < 4; nfp++) {
                uint32_t boff = ((noff + nfp * 16 + bRow) * RSTR + kc * 8 + bCol) * 4;
                uint32_t bf[4];
                ldm4(bf, smB + boff);
#pragma unroll
                for (int snf = 0; snf < 2; snf++) {
                    int nf = nfp * 2 + snf;
#pragma unroll
                    for (int mf = 0; mf < 2; mf++)
                        mma_f16(acc[mf][nf],
                                reinterpret_cast<uint32_t*>(&af4[kc][mf]),
                                &bf[2 * snf]);
                }
            }
        }

        if (have) {
            storeB(buf ^ 1, vpre);   // vpre dies here...
            loadA(af4, s + 1);       // ...freeing regs for next A fragments
        }
    }

    // epilogue
    __syncthreads();
    float* Cs = (float*)smem;                // 128 x 132 fp32 (67584 B)
#pragma unroll
    for (int mf = 0; mf < 2; mf++) {
#pragma unroll
        for (int nf = 0; nf < 8; nf++) {
            int m0 = moff + mf * 16 + gid;
            int nl = noff + nf * 8 + 2 * tig;
            *(float2*)&Cs[m0 * 132 + nl]       = make_float2(acc[mf][nf][0], acc[mf][nf][1]);
            *(float2*)&Cs[(m0 + 8) * 132 + nl] = make_float2(acc[mf][nf][2], acc[mf][nf][3]);
        }
    }
    __syncthreads();

    for (int t = warp; t < 128; t += 8) {
        const int oc = oc0 + t;
        const float g  = bn[oc];
        const float be = bn[256 + oc];
        const float mm = bn[512 + oc];
        const float vv = bn[768 + oc];
        const float inv  = g * rsqrtf(vv + EPS_);
        const float bias = be - mm * inv;
#pragma unroll
        for (int cc0 = 0; cc0 < 128; cc0 += 32) {
            int cc = cc0 + lane;
            int n = p0 + cc;
            if (n < NP) {
                float val = Cs[t * 132 + cc] * inv + bias;
                if (RELU) val = fmaxf(val, 0.f);
                if (EPI == 0) {
                    int b = n / PXB; int rq = n - b * PXB;
                    out[((size_t)(b * 256 + oc)) * PXB + rq] = val;
                } else {
                    __half hv = __float2half_rn(val);
                    outF[(size_t)(oc >> 1) * 80000 + n * 2 + (oc & 1)] =
                        *reinterpret_cast<uint16_t*>(&hv);
                }
            }
        }
    }
}

// ---------------------------------------------------------------------------
// Multi-scale depthwise xcorr, paired channels, single fp16 packed output.
// ---------------------------------------------------------------------------
__global__ void multixcorr_kernel(const float* __restrict__ s,
                                  const float* __restrict__ k,
                                  uint32_t* __restrict__ ff) {
    const int kp0 = blockIdx.x;   // 0..127
    const int b   = blockIdx.y;

    __shared__ float ss[2][841];
    __shared__ float kk[2][25];

    const float* sp = s + ((size_t)b * HID_ + 2 * kp0) * 841;
    const float* kp = k + ((size_t)b * HID_ + 2 * kp0) * 25;

    for (int i = threadIdx.x; i < 2 * 841; i += blockDim.x)
        ss[i / 841][i % 841] = sp[i];
    if (threadIdx.x < 50) kk[threadIdx.x / 25][threadIdx.x % 25] = kp[threadIdx.x];
    __syncthreads();

    for (int p = threadIdx.x; p < 625; p += blockDim.x) {
        const int y = p / 25, x = p - (p / 25) * 25;
        float f0[2], f1[2], f2[2];
#pragma unroll
        for (int h = 0; h < 2; h++) {
            float s_full = 0.f, s_in = 0.f;
#pragma unroll
            for (int dy = 0; dy < 5; dy++)
#pragma unroll
                for (int dx = 0; dx < 5; dx++) {
                    float vv = ss[h][(y + dy) * 29 + (x + dx)] * kk[h][dy * 5 + dx];
                    s_full += vv;
                    if (dy >= 1 && dy <= 3 && dx >= 1 && dx <= 3) s_in += vv;
                }
            f0[h] = s_full;
            f1[h] = s_in;
            f2[h] = ss[h][(y + 2) * 29 + (x + 2)] * kk[h][12];
        }
        const int n = b * 625 + p;
        ff[(size_t)kp0 * 40000 + n]         = pack2h(f0[0], f0[1]);
        ff[(size_t)(128 + kp0) * 40000 + n] = pack2h(f1[0], f1[1]);
        ff[(size_t)(256 + kp0) * 40000 + n] = pack2h(f2[0], f2[1]);
    }
}

// ---------------------------------------------------------------------------
// Final 1x1: (B,256,625) x (10,256) + bias -> (B,10,625). grid (B, 5).
// ---------------------------------------------------------------------------
__global__ void conv1x1_out_kernel(const float* __restrict__ in,
                                   const float* __restrict__ w,
                                   const float* __restrict__ bias,
                                   float* __restrict__ out) {
    const int b = blockIdx.x;
    const int chunk = blockIdx.y;

    __shared__ float wsm[COUT_ * HID_];
    for (int i = threadIdx.x; i < COUT_ * HID_; i += blockDim.x) wsm[i] = w[i];
    __syncthreads();

    const float* ib = in + (size_t)b * HID_ * 625;
    float* ob = out + (size_t)b * COUT_ * 625;

    const int pend = min(625, (chunk + 1) * 125);
    for (int p = chunk * 125 + threadIdx.x; p < pend; p += blockDim.x) {
        float acc[COUT_];
#pragma unroll
        for (int o = 0; o < COUT_; o++) acc[o] = bias[o];
        for (int c = 0; c < HID_; c++) {
            float vv = ib[(size_t)c * 625 + p];
#pragma unroll
            for (int o = 0; o < COUT_; o++) acc[o] = fmaf(vv, wsm[o * HID_ + c], acc[o]);
        }
#pragma unroll
        for (int o = 0; o < COUT_; o++) ob[(size_t)o * 625 + p] = acc[o];
    }
}

// ---------------------------------------------------------------------------
extern "C" void kernel_launch(void* const* d_in, const int* in_sizes, int n_in,
                              void* d_out, int out_size) {
    const float* kernel_in = (const float*)d_in[0];
    const float* search_in = (const float*)d_in[1];
    const float* wk  = (const float*)d_in[2];
    const float* bnk = (const float*)d_in[3];
    const float* ws  = (const float*)d_in[4];
    const float* bns = (const float*)d_in[5];
    const float* wd  = (const float*)d_in[6];
    const float* bnd = (const float*)d_in[7];
    const float* wh1 = (const float*)d_in[8];
    const float* bnh = (const float*)d_in[9];
    const float* wh2 = (const float*)d_in[10];
    const float* bh2 = (const float*)d_in[11];
    float* out = (float*)d_out;

    float *kfeat, *sfeat, *h;
    uint4 *wkA, *wsA, *wdA, *wh1A;
    uint32_t *kinF, *sinF, *featF, *f2F;
    cudaGetSymbolAddress((void**)&kfeat, g_kfeat);
    cudaGetSymbolAddress((void**)&sfeat, g_sfeat);
    cudaGetSymbolAddress((void**)&h,     g_h);
    cudaGetSymbolAddress((void**)&wkA, g_wkA);
    cudaGetSymbolAddress((void**)&wsA, g_wsA);
    cudaGetSymbolAddress((void**)&wdA, g_wdA);
    cudaGetSymbolAddress((void**)&wh1A, g_wh1A);
    cudaGetSymbolAddress((void**)&kinF, g_kinF);
    cudaGetSymbolAddress((void**)&sinF, g_sinF);
    cudaGetSymbolAddress((void**)&featF, g_featF);
    cudaGetSymbolAddress((void**)&f2F, g_f2F);

    constexpr int SMEM = 128 * 132 * 4;   // 67584 (B staging 2x10240 B < epi)

    cudaFuncSetAttribute(gemm_f16_kernel<0, 7, 7, 2304, true, 0>,
                         cudaFuncAttributeMaxDynamicSharedMemorySize, SMEM);
    cudaFuncSetAttribute(gemm_f16_kernel<0, 31, 31, 2304, true, 0>,
                         cudaFuncAttributeMaxDynamicSharedMemorySize, SMEM);
    cudaFuncSetAttribute(gemm_f16_kernel<1, 3, 3, 768, false, 1>,
                         cudaFuncAttributeMaxDynamicSharedMemorySize, SMEM);
    cudaFuncSetAttribute(gemm_f16_kernel<1, 3, 3, 256, true, 0>,
                         cudaFuncAttributeMaxDynamicSharedMemorySize, SMEM);

    // #0-#2: dependencies of gemm_s (ncu window = launch index 3)
    prep_in_f16<961><<<(128 * 64 * 961 + 255) / 256, 256>>>(search_in, sinF);   // 0
    prep_w3_frag<<<(16 * 144 * 32 + 255) / 256, 256>>>(ws, wsA);                // 1
    prep_w1_frag<768><<<(16 * 48 * 32 + 255) / 256, 256>>>(wd, wdA);            // 2

    // #3: search branch conv3x3 -> g_sfeat  [PROFILED]
    gemm_f16_kernel<0, 31, 31, 2304, true, 0><<<dim3(421, 2), 256, SMEM>>>(
        sinF, wsA, bns, sfeat, nullptr);

    // remaining preps
    prep_w3_frag<<<(16 * 144 * 32 + 255) / 256, 256>>>(wk, wkA);                // 4
    prep_w1_frag<256><<<(16 * 16 * 32 + 255) / 256, 256>>>(wh1, wh1A);          // 5
    prep_in_f16<49><<<(128 * 64 * 49 + 255) / 256, 256>>>(kernel_in, kinF);     // 6

    // kernel branch conv3x3 -> g_kfeat
    gemm_f16_kernel<0, 7, 7, 2304, true, 0><<<dim3(13, 2), 256, SMEM>>>(
        kinF, wkA, bnk, kfeat, nullptr);
    // xcorr -> packed featF (single fp16)
    multixcorr_kernel<<<dim3(128, B_), 256>>>(sfeat, kfeat, featF);
    // wd + bn -> packed f2F
    gemm_f16_kernel<1, 3, 3, 768, false, 1><<<dim3(313, 2), 256, SMEM>>>(
        featF, wdA, bnd, nullptr, (uint16_t*)f2F);
    // wh1 + bn + relu -> g_h
    gemm_f16_kernel<1, 3, 3, 256, true, 0><<<dim3(313, 2), 256, SMEM>>>(
        f2F, wh1A, bnh, h, nullptr);
    // wh2 + bias -> out
    conv1x1_out_kernel<<<dim3(B_, 5), 128>>>(h, wh2, bh2, out);
}